// round 2
// baseline (speedup 1.0000x reference)
#include <cuda_runtime.h>

// Problem constants
#define Bb   2
#define Ss   2048
#define Dd   1024
#define Hh   16
#define DKh  64
#define Mtot (Bb * Ss)   // 4096

// Scratch (device globals; no allocations allowed)
__device__ float g_q[Mtot * Dd];
__device__ float g_k[Mtot * Dd];
__device__ float g_v[Mtot * Dd];
__device__ float g_o[Mtot * Dd];

// ---------------------------------------------------------------------------
// SGEMM with bias: C[M,N] = (A[M,K] * W[K,N] + bias[N]) * scale
// 128x128 block tile, BK=8, 256 threads, 8x8 micro-tile per thread.
// ---------------------------------------------------------------------------
#define BM 128
#define BN 128
#define BKK 8
#define TM 8
#define TN 8

__global__ __launch_bounds__(256) void sgemm_bias(
    const float* __restrict__ A, const float* __restrict__ W,
    const float* __restrict__ bias, float* __restrict__ C,
    int M, int N, int K, float scale)
{
    __shared__ float As[BKK * BM];   // transposed: As[k][m]
    __shared__ float Bs[BKK * BN];   // natural:    Bs[k][n]

    const int t  = threadIdx.x;
    const int tx = t & 15;          // 0..15 -> col group
    const int ty = t >> 4;          // 0..15 -> row group
    const int row0 = blockIdx.y * BM;
    const int col0 = blockIdx.x * BN;

    const int aRow = t >> 1;            // 0..127
    const int aCol = (t & 1) * 4;       // 0 or 4
    const int bRow = t >> 5;            // 0..7
    const int bCol = (t & 31) * 4;      // 0..124

    const float* Ap = A + (size_t)(row0 + aRow) * K + aCol;
    const float* Wp = W + (size_t)bRow * N + col0 + bCol;

    float acc[TM][TN];
#pragma unroll
    for (int i = 0; i < TM; i++)
#pragma unroll
        for (int j = 0; j < TN; j++) acc[i][j] = 0.f;

    for (int k0 = 0; k0 < K; k0 += BKK) {
        float4 av = *(const float4*)Ap;
        As[(aCol + 0) * BM + aRow] = av.x;
        As[(aCol + 1) * BM + aRow] = av.y;
        As[(aCol + 2) * BM + aRow] = av.z;
        As[(aCol + 3) * BM + aRow] = av.w;
        *(float4*)&Bs[bRow * BN + bCol] = *(const float4*)Wp;
        __syncthreads();
        Ap += BKK;
        Wp += (size_t)BKK * N;

#pragma unroll
        for (int k = 0; k < BKK; k++) {
            float4 a0 = *(const float4*)&As[k * BM + ty * TM];
            float4 a1 = *(const float4*)&As[k * BM + ty * TM + 4];
            float4 b0 = *(const float4*)&Bs[k * BN + tx * TN];
            float4 b1 = *(const float4*)&Bs[k * BN + tx * TN + 4];
            float a[TM] = {a0.x, a0.y, a0.z, a0.w, a1.x, a1.y, a1.z, a1.w};
            float b[TN] = {b0.x, b0.y, b0.z, b0.w, b1.x, b1.y, b1.z, b1.w};
#pragma unroll
            for (int i = 0; i < TM; i++)
#pragma unroll
                for (int j = 0; j < TN; j++)
                    acc[i][j] += a[i] * b[j];
        }
        __syncthreads();
    }

    float bv[TN];
#pragma unroll
    for (int j = 0; j < TN; j++) bv[j] = bias[col0 + tx * TN + j];

#pragma unroll
    for (int i = 0; i < TM; i++) {
        float4 o0, o1;
        o0.x = (acc[i][0] + bv[0]) * scale;
        o0.y = (acc[i][1] + bv[1]) * scale;
        o0.z = (acc[i][2] + bv[2]) * scale;
        o0.w = (acc[i][3] + bv[3]) * scale;
        o1.x = (acc[i][4] + bv[4]) * scale;
        o1.y = (acc[i][5] + bv[5]) * scale;
        o1.z = (acc[i][6] + bv[6]) * scale;
        o1.w = (acc[i][7] + bv[7]) * scale;
        float* cp = C + (size_t)(row0 + ty * TM + i) * N + col0 + tx * TN;
        *(float4*)cp       = o0;
        *(float4*)(cp + 4) = o1;
    }
}

// ---------------------------------------------------------------------------
// Flash attention: one block per (b,h, 64-query tile). DK=64, key tiles of 64.
// Q already pre-scaled by 1/sqrt(DK). 48KB static smem exactly.
// Thread mapping: t = ty*8 + tx ; owns rows {ty, ty+32}, cols tx*8..tx*8+7.
// ---------------------------------------------------------------------------
#define BQ 64
#define BKT 64

__global__ __launch_bounds__(256) void attn_kernel(
    const float* __restrict__ Qm, const float* __restrict__ Km,
    const float* __restrict__ Vm, float* __restrict__ Om)
{
    __shared__ float Qs[64 * 64];    // [dk][r]  (transposed)
    __shared__ float KVs[64 * 64];   // K phase: [dk][c] ; V phase: [c][dk]
    __shared__ float Ps[64 * 64];    // [c][r]

    const int t  = threadIdx.x;
    const int tx = t & 7;            // col group (8 cols each)
    const int ty = t >> 3;           // 0..31 -> rows ty, ty+32
    const int bh = blockIdx.x;       // 0..31
    const int b  = bh >> 4;
    const int h  = bh & 15;
    const int q0 = blockIdx.y * BQ;

    const float* Qg = Qm + (size_t)(b * Ss + q0) * Dd + h * DKh;
    const float* Kg = Km + (size_t)(b * Ss) * Dd + h * DKh;
    const float* Vg = Vm + (size_t)(b * Ss) * Dd + h * DKh;

    // Load Q tile transposed into smem: Qs[dk][r]
    {
        const int lr  = t >> 2;          // 0..63 (query row in tile)
        const int dk0 = (t & 3) * 16;
#pragma unroll
        for (int i = 0; i < 4; i++) {
            float4 v = *(const float4*)(Qg + (size_t)lr * Dd + dk0 + i * 4);
            Qs[(dk0 + i * 4 + 0) * 64 + lr] = v.x;
            Qs[(dk0 + i * 4 + 1) * 64 + lr] = v.y;
            Qs[(dk0 + i * 4 + 2) * 64 + lr] = v.z;
            Qs[(dk0 + i * 4 + 3) * 64 + lr] = v.w;
        }
    }

    float m0 = -INFINITY, m1 = -INFINITY;
    float l0 = 0.f, l1 = 0.f;
    float o0[8], o1[8];
#pragma unroll
    for (int j = 0; j < 8; j++) { o0[j] = 0.f; o1[j] = 0.f; }

    for (int kt = 0; kt < Ss; kt += BKT) {
        // Load K tile transposed: KVs[dk][c]
        {
            const int lr  = t >> 2;
            const int dk0 = (t & 3) * 16;
#pragma unroll
            for (int i = 0; i < 4; i++) {
                float4 v = *(const float4*)(Kg + (size_t)(kt + lr) * Dd + dk0 + i * 4);
                KVs[(dk0 + i * 4 + 0) * 64 + lr] = v.x;
                KVs[(dk0 + i * 4 + 1) * 64 + lr] = v.y;
                KVs[(dk0 + i * 4 + 2) * 64 + lr] = v.z;
                KVs[(dk0 + i * 4 + 3) * 64 + lr] = v.w;
            }
        }
        __syncthreads();   // also covers the Q load on first iteration

        // Scores: s[r][c] = sum_dk Q[r][dk] * K[c][dk]
        float s0[8], s1[8];
#pragma unroll
        for (int j = 0; j < 8; j++) { s0[j] = 0.f; s1[j] = 0.f; }
#pragma unroll 4
        for (int k = 0; k < 64; k++) {
            float qa = Qs[k * 64 + ty];
            float qb = Qs[k * 64 + ty + 32];
            float4 k0v = *(const float4*)&KVs[k * 64 + tx * 8];
            float4 k1v = *(const float4*)&KVs[k * 64 + tx * 8 + 4];
            float kv[8] = {k0v.x, k0v.y, k0v.z, k0v.w, k1v.x, k1v.y, k1v.z, k1v.w};
#pragma unroll
            for (int j = 0; j < 8; j++) {
                s0[j] += qa * kv[j];
                s1[j] += qb * kv[j];
            }
        }

        // Online softmax (row reduction over the 8 threads of each row)
        float mt0 = s0[0], mt1 = s1[0];
#pragma unroll
        for (int j = 1; j < 8; j++) { mt0 = fmaxf(mt0, s0[j]); mt1 = fmaxf(mt1, s1[j]); }
#pragma unroll
        for (int off = 1; off < 8; off <<= 1) {
            mt0 = fmaxf(mt0, __shfl_xor_sync(0xffffffffu, mt0, off));
            mt1 = fmaxf(mt1, __shfl_xor_sync(0xffffffffu, mt1, off));
        }
        float mn0 = fmaxf(m0, mt0), mn1 = fmaxf(m1, mt1);
        float c0 = __expf(m0 - mn0), c1 = __expf(m1 - mn1);

        float sum0 = 0.f, sum1 = 0.f;
#pragma unroll
        for (int j = 0; j < 8; j++) {
            float p0 = __expf(s0[j] - mn0);
            float p1 = __expf(s1[j] - mn1);
            sum0 += p0; sum1 += p1;
            Ps[(tx * 8 + j) * 64 + ty]      = p0;
            Ps[(tx * 8 + j) * 64 + ty + 32] = p1;
        }
#pragma unroll
        for (int off = 1; off < 8; off <<= 1) {
            sum0 += __shfl_xor_sync(0xffffffffu, sum0, off);
            sum1 += __shfl_xor_sync(0xffffffffu, sum1, off);
        }
        l0 = l0 * c0 + sum0;
        l1 = l1 * c1 + sum1;
        m0 = mn0; m1 = mn1;
#pragma unroll
        for (int j = 0; j < 8; j++) { o0[j] *= c0; o1[j] *= c1; }

        __syncthreads();   // Ks reads done, Ps writes visible

        // Load V tile natural: KVs[c][dk]
        {
            const int lr  = t >> 2;
            const int dk0 = (t & 3) * 16;
#pragma unroll
            for (int i = 0; i < 4; i++)
                *(float4*)&KVs[lr * 64 + dk0 + i * 4] =
                    *(const float4*)(Vg + (size_t)(kt + lr) * Dd + dk0 + i * 4);
        }
        __syncthreads();

        // O += P * V
#pragma unroll 4
        for (int c = 0; c < 64; c++) {
            float p0 = Ps[c * 64 + ty];
            float p1 = Ps[c * 64 + ty + 32];
            float4 v0 = *(const float4*)&KVs[c * 64 + tx * 8];
            float4 v1 = *(const float4*)&KVs[c * 64 + tx * 8 + 4];
            float vv[8] = {v0.x, v0.y, v0.z, v0.w, v1.x, v1.y, v1.z, v1.w};
#pragma unroll
            for (int j = 0; j < 8; j++) {
                o0[j] += p0 * vv[j];
                o1[j] += p1 * vv[j];
            }
        }
        __syncthreads();   // done with Vs/Ps before next tile overwrites
    }

    // Finalize and write to concat layout [B,S,D]
    float r0 = 1.f / l0, r1 = 1.f / l1;
    float* Og = Om + (size_t)(b * Ss + q0) * Dd + h * DKh;
    float4 w;
    w.x = o0[0] * r0; w.y = o0[1] * r0; w.z = o0[2] * r0; w.w = o0[3] * r0;
    *(float4*)(Og + (size_t)ty * Dd + tx * 8) = w;
    w.x = o0[4] * r0; w.y = o0[5] * r0; w.z = o0[6] * r0; w.w = o0[7] * r0;
    *(float4*)(Og + (size_t)ty * Dd + tx * 8 + 4) = w;
    w.x = o1[0] * r1; w.y = o1[1] * r1; w.z = o1[2] * r1; w.w = o1[3] * r1;
    *(float4*)(Og + (size_t)(ty + 32) * Dd + tx * 8) = w;
    w.x = o1[4] * r1; w.y = o1[5] * r1; w.z = o1[6] * r1; w.w = o1[7] * r1;
    *(float4*)(Og + (size_t)(ty + 32) * Dd + tx * 8 + 4) = w;
}

// ---------------------------------------------------------------------------
// Launch
// ---------------------------------------------------------------------------
extern "C" void kernel_launch(void* const* d_in, const int* in_sizes, int n_in,
                              void* d_out, int out_size)
{
    const float* x  = (const float*)d_in[0];
    const float* Wq = (const float*)d_in[1];
    const float* bq = (const float*)d_in[2];
    const float* Wk = (const float*)d_in[3];
    const float* bk = (const float*)d_in[4];
    const float* Wv = (const float*)d_in[5];
    const float* bv = (const float*)d_in[6];
    const float* Wo = (const float*)d_in[7];
    const float* bo = (const float*)d_in[8];
    float* out = (float*)d_out;

    float *q, *k, *v, *o;
    cudaGetSymbolAddress((void**)&q, g_q);
    cudaGetSymbolAddress((void**)&k, g_k);
    cudaGetSymbolAddress((void**)&v, g_v);
    cudaGetSymbolAddress((void**)&o, g_o);

    dim3 gGrid(Dd / BN, Mtot / BM);   // (8, 32)
    const float qscale = 0.125f;      // 1/sqrt(DK), folded into Q (incl. bias)

    sgemm_bias<<<gGrid, 256>>>(x, Wq, bq, q, Mtot, Dd, Dd, qscale);
    sgemm_bias<<<gGrid, 256>>>(x, Wk, bk, k, Mtot, Dd, Dd, 1.0f);
    sgemm_bias<<<gGrid, 256>>>(x, Wv, bv, v, Mtot, Dd, Dd, 1.0f);

    attn_kernel<<<dim3(Bb * Hh, Ss / BQ), 256>>>(q, k, v, o);

    sgemm_bias<<<gGrid, 256>>>(o, Wo, bo, out, Mtot, Dd, Dd, 1.0f);
}

// round 4
// speedup vs baseline: 1.1885x; 1.1885x over previous
#include <cuda_runtime.h>
#include <cuda_bf16.h>
#include <cstdint>

#define Bb   2
#define Ss   2048
#define Dd   1024
#define Hh   16
#define DKh  64
#define Mtot (Bb * Ss)

__device__ float g_q[Mtot * Dd];
__device__ float g_k[Mtot * Dd];
__device__ float g_v[Mtot * Dd];
__device__ float g_o[Mtot * Dd];
__device__ float g_wt[4u * Dd * Dd];

// ---------------------------------------------------------------------------
// Weight transpose: Wt[n][k] = W[k][n], 1024x1024
// ---------------------------------------------------------------------------
__global__ __launch_bounds__(256) void transpose_w(const float* __restrict__ W, float* __restrict__ Wt)
{
    __shared__ float tile[32][33];
    int bx = blockIdx.x * 32, by = blockIdx.y * 32;
    int tx = threadIdx.x & 31, ty8 = threadIdx.x >> 5;
#pragma unroll
    for (int i = 0; i < 4; i++)
        tile[ty8 + i * 8][tx] = W[(size_t)(by + ty8 + i * 8) * Dd + bx + tx];
    __syncthreads();
#pragma unroll
    for (int i = 0; i < 4; i++)
        Wt[(size_t)(bx + ty8 + i * 8) * Dd + by + tx] = tile[tx][ty8 + i * 8];
}

// ---------------------------------------------------------------------------
// 3xBF16 mma.sync GEMM: C[M,N] = (A[M,K] @ Wt[N,K]^T + bias) * scale
// CTA 128x128, BK=32, 256 thr (8 warps, 4x2), warp tile 32x64, double buffer.
// SMEM row stride 40 bf16 (80B) -> conflict-free frag loads.
// ---------------------------------------------------------------------------
#define RS   40              // smem row stride in bf16
#define TILEB (128 * RS * 2) // 10240 bytes per tile
#define SBUF  (4 * TILEB)    // Ah, Al, Bh, Bl per buffer = 40960
#define SMTOT (2 * SBUF)     // 81920

__device__ __forceinline__ void mma_bf16(float* c, const uint32_t* a, uint32_t b0, uint32_t b1)
{
    asm volatile(
        "mma.sync.aligned.m16n8k16.row.col.f32.bf16.bf16.f32 "
        "{%0,%1,%2,%3},{%4,%5,%6,%7},{%8,%9},{%0,%1,%2,%3};"
        : "+f"(c[0]), "+f"(c[1]), "+f"(c[2]), "+f"(c[3])
        : "r"(a[0]), "r"(a[1]), "r"(a[2]), "r"(a[3]), "r"(b0), "r"(b1));
}

__device__ __forceinline__ void split_sts(__nv_bfloat16* hiP, __nv_bfloat16* loP, float4 a)
{
    __nv_bfloat162 h0 = __float22bfloat162_rn(make_float2(a.x, a.y));
    __nv_bfloat162 h1 = __float22bfloat162_rn(make_float2(a.z, a.w));
    float2 f0 = __bfloat1622float2(h0), f1 = __bfloat1622float2(h1);
    __nv_bfloat162 l0 = __float22bfloat162_rn(make_float2(a.x - f0.x, a.y - f0.y));
    __nv_bfloat162 l1 = __float22bfloat162_rn(make_float2(a.z - f1.x, a.w - f1.y));
    *(uint2*)hiP = make_uint2(*(uint32_t*)&h0, *(uint32_t*)&h1);
    *(uint2*)loP = make_uint2(*(uint32_t*)&l0, *(uint32_t*)&l1);
}

__global__ __launch_bounds__(256, 1) void gemm_bf16x3(
    const float* __restrict__ A, const float* __restrict__ Wt,
    const float* __restrict__ bias, float* __restrict__ C, float scale)
{
    extern __shared__ __align__(16) char smem[];
    const int t = threadIdx.x, l = t & 31, wid = t >> 5;
    const int wm = wid >> 1, wn = wid & 1;
    const int row0 = blockIdx.y * 128, col0 = blockIdx.x * 128;
    const int lr = l >> 2, lc = (l & 3) * 2;

    float acc[2][8][4];
#pragma unroll
    for (int mt = 0; mt < 2; mt++)
#pragma unroll
        for (int nt = 0; nt < 8; nt++)
#pragma unroll
            for (int j = 0; j < 4; j++) acc[mt][nt][j] = 0.f;

    float4 av[4], bv[4];
    // prologue: load+store chunk 0 into buffer 0
#pragma unroll
    for (int i = 0; i < 4; i++) {
        int f = t + i * 256, r = f >> 3, q = f & 7;
        av[i] = *(const float4*)(A  + (size_t)(row0 + r) * Dd + q * 4);
        bv[i] = *(const float4*)(Wt + (size_t)(col0 + r) * Dd + q * 4);
    }
#pragma unroll
    for (int i = 0; i < 4; i++) {
        int f = t + i * 256, r = f >> 3, q = f & 7;
        __nv_bfloat16* base = (__nv_bfloat16*)smem;
        split_sts(base + 0 * (TILEB / 2) + r * RS + q * 4,
                  base + 1 * (TILEB / 2) + r * RS + q * 4, av[i]);
        split_sts(base + 2 * (TILEB / 2) + r * RS + q * 4,
                  base + 3 * (TILEB / 2) + r * RS + q * 4, bv[i]);
    }
    __syncthreads();

    for (int ch = 0; ch < 32; ch++) {
        const int cur = ch & 1;
        if (ch < 31) {
            const int k0 = (ch + 1) * 32;
#pragma unroll
            for (int i = 0; i < 4; i++) {
                int f = t + i * 256, r = f >> 3, q = f & 7;
                av[i] = *(const float4*)(A  + (size_t)(row0 + r) * Dd + k0 + q * 4);
                bv[i] = *(const float4*)(Wt + (size_t)(col0 + r) * Dd + k0 + q * 4);
            }
        }

        const __nv_bfloat16* Ah = (const __nv_bfloat16*)(smem + cur * SBUF);
        const __nv_bfloat16* Al = Ah + TILEB / 2;
        const __nv_bfloat16* Bh = Al + TILEB / 2;
        const __nv_bfloat16* Bl = Bh + TILEB / 2;

#pragma unroll
        for (int kk = 0; kk < 2; kk++) {
            const int kb = kk * 16 + lc;
            uint32_t ah[2][4], al[2][4];
#pragma unroll
            for (int mt = 0; mt < 2; mt++) {
                int r = wm * 32 + mt * 16 + lr;
                ah[mt][0] = *(const uint32_t*)&Ah[r * RS + kb];
                ah[mt][1] = *(const uint32_t*)&Ah[(r + 8) * RS + kb];
                ah[mt][2] = *(const uint32_t*)&Ah[r * RS + kb + 8];
                ah[mt][3] = *(const uint32_t*)&Ah[(r + 8) * RS + kb + 8];
                al[mt][0] = *(const uint32_t*)&Al[r * RS + kb];
                al[mt][1] = *(const uint32_t*)&Al[(r + 8) * RS + kb];
                al[mt][2] = *(const uint32_t*)&Al[r * RS + kb + 8];
                al[mt][3] = *(const uint32_t*)&Al[(r + 8) * RS + kb + 8];
            }
#pragma unroll
            for (int nt = 0; nt < 8; nt++) {
                int rn = wn * 64 + nt * 8 + lr;
                uint32_t bh0 = *(const uint32_t*)&Bh[rn * RS + kb];
                uint32_t bh1 = *(const uint32_t*)&Bh[rn * RS + kb + 8];
                uint32_t bl0 = *(const uint32_t*)&Bl[rn * RS + kb];
                uint32_t bl1 = *(const uint32_t*)&Bl[rn * RS + kb + 8];
#pragma unroll
                for (int mt = 0; mt < 2; mt++) {
                    mma_bf16(acc[mt][nt], ah[mt], bh0, bh1);
                    mma_bf16(acc[mt][nt], ah[mt], bl0, bl1);
                    mma_bf16(acc[mt][nt], al[mt], bh0, bh1);
                }
            }
        }

        if (ch < 31) {
            const int nxt = 1 - cur;
            __nv_bfloat16* base = (__nv_bfloat16*)(smem + nxt * SBUF);
#pragma unroll
            for (int i = 0; i < 4; i++) {
                int f = t + i * 256, r = f >> 3, q = f & 7;
                split_sts(base + 0 * (TILEB / 2) + r * RS + q * 4,
                          base + 1 * (TILEB / 2) + r * RS + q * 4, av[i]);
                split_sts(base + 2 * (TILEB / 2) + r * RS + q * 4,
                          base + 3 * (TILEB / 2) + r * RS + q * 4, bv[i]);
            }
        }
        __syncthreads();
    }

    // Epilogue: bias + scale, write fp32
#pragma unroll
    for (int mt = 0; mt < 2; mt++) {
        const int r0 = row0 + wm * 32 + mt * 16 + lr;
#pragma unroll
        for (int nt = 0; nt < 8; nt++) {
            const int c = col0 + wn * 64 + nt * 8 + lc;
            float2 bb = *(const float2*)&bias[c];
            float2 v0 = make_float2((acc[mt][nt][0] + bb.x) * scale,
                                    (acc[mt][nt][1] + bb.y) * scale);
            float2 v1 = make_float2((acc[mt][nt][2] + bb.x) * scale,
                                    (acc[mt][nt][3] + bb.y) * scale);
            *(float2*)(C + (size_t)r0 * Dd + c)       = v0;
            *(float2*)(C + (size_t)(r0 + 8) * Dd + c) = v1;
        }
    }
}

// ---------------------------------------------------------------------------
// Flash attention (unchanged): block = (b,h,64-query tile)
// ---------------------------------------------------------------------------
#define BQ 64
#define BKT 64

__global__ __launch_bounds__(256) void attn_kernel(
    const float* __restrict__ Qm, const float* __restrict__ Km,
    const float* __restrict__ Vm, float* __restrict__ Om)
{
    __shared__ float Qs[64 * 64];
    __shared__ float KVs[64 * 64];
    __shared__ float Ps[64 * 64];

    const int t = threadIdx.x;
    const int tx = t & 7;
    const int ty = t >> 3;
    const int bh = blockIdx.x;
    const int b = bh >> 4;
    const int h = bh & 15;
    const int q0 = blockIdx.y * BQ;

    const float* Qg = Qm + (size_t)(b * Ss + q0) * Dd + h * DKh;
    const float* Kg = Km + (size_t)(b * Ss) * Dd + h * DKh;
    const float* Vg = Vm + (size_t)(b * Ss) * Dd + h * DKh;

    {
        const int lr = t >> 2, dk0 = (t & 3) * 16;
#pragma unroll
        for (int i = 0; i < 4; i++) {
            float4 v = *(const float4*)(Qg + (size_t)lr * Dd + dk0 + i * 4);
            Qs[(dk0 + i * 4 + 0) * 64 + lr] = v.x;
            Qs[(dk0 + i * 4 + 1) * 64 + lr] = v.y;
            Qs[(dk0 + i * 4 + 2) * 64 + lr] = v.z;
            Qs[(dk0 + i * 4 + 3) * 64 + lr] = v.w;
        }
    }

    float m0 = -INFINITY, m1 = -INFINITY, l0 = 0.f, l1 = 0.f;
    float o0[8], o1[8];
#pragma unroll
    for (int j = 0; j < 8; j++) { o0[j] = 0.f; o1[j] = 0.f; }

    for (int kt = 0; kt < Ss; kt += BKT) {
        {
            const int lr = t >> 2, dk0 = (t & 3) * 16;
#pragma unroll
            for (int i = 0; i < 4; i++) {
                float4 v = *(const float4*)(Kg + (size_t)(kt + lr) * Dd + dk0 + i * 4);
                KVs[(dk0 + i * 4 + 0) * 64 + lr] = v.x;
                KVs[(dk0 + i * 4 + 1) * 64 + lr] = v.y;
                KVs[(dk0 + i * 4 + 2) * 64 + lr] = v.z;
                KVs[(dk0 + i * 4 + 3) * 64 + lr] = v.w;
            }
        }
        __syncthreads();

        float s0[8], s1[8];
#pragma unroll
        for (int j = 0; j < 8; j++) { s0[j] = 0.f; s1[j] = 0.f; }
#pragma unroll 4
        for (int k = 0; k < 64; k++) {
            float qa = Qs[k * 64 + ty];
            float qb = Qs[k * 64 + ty + 32];
            float4 k0v = *(const float4*)&KVs[k * 64 + tx * 8];
            float4 k1v = *(const float4*)&KVs[k * 64 + tx * 8 + 4];
            float kv[8] = {k0v.x, k0v.y, k0v.z, k0v.w, k1v.x, k1v.y, k1v.z, k1v.w};
#pragma unroll
            for (int j = 0; j < 8; j++) { s0[j] += qa * kv[j]; s1[j] += qb * kv[j]; }
        }

        float mt0 = s0[0], mt1 = s1[0];
#pragma unroll
        for (int j = 1; j < 8; j++) { mt0 = fmaxf(mt0, s0[j]); mt1 = fmaxf(mt1, s1[j]); }
#pragma unroll
        for (int off = 1; off < 8; off <<= 1) {
            mt0 = fmaxf(mt0, __shfl_xor_sync(0xffffffffu, mt0, off));
            mt1 = fmaxf(mt1, __shfl_xor_sync(0xffffffffu, mt1, off));
        }
        float mn0 = fmaxf(m0, mt0), mn1 = fmaxf(m1, mt1);
        float c0 = __expf(m0 - mn0), c1 = __expf(m1 - mn1);

        float sum0 = 0.f, sum1 = 0.f;
#pragma unroll
        for (int j = 0; j < 8; j++) {
            float p0 = __expf(s0[j] - mn0);
            float p1 = __expf(s1[j] - mn1);
            sum0 += p0; sum1 += p1;
            Ps[(tx * 8 + j) * 64 + ty] = p0;
            Ps[(tx * 8 + j) * 64 + ty + 32] = p1;
        }
#pragma unroll
        for (int off = 1; off < 8; off <<= 1) {
            sum0 += __shfl_xor_sync(0xffffffffu, sum0, off);
            sum1 += __shfl_xor_sync(0xffffffffu, sum1, off);
        }
        l0 = l0 * c0 + sum0; l1 = l1 * c1 + sum1;
        m0 = mn0; m1 = mn1;
#pragma unroll
        for (int j = 0; j < 8; j++) { o0[j] *= c0; o1[j] *= c1; }

        __syncthreads();

        {
            const int lr = t >> 2, dk0 = (t & 3) * 16;
#pragma unroll
            for (int i = 0; i < 4; i++)
                *(float4*)&KVs[lr * 64 + dk0 + i * 4] =
                    *(const float4*)(Vg + (size_t)(kt + lr) * Dd + dk0 + i * 4);
        }
        __syncthreads();

#pragma unroll 4
        for (int c = 0; c < 64; c++) {
            float p0 = Ps[c * 64 + ty];
            float p1 = Ps[c * 64 + ty + 32];
            float4 v0 = *(const float4*)&KVs[c * 64 + tx * 8];
            float4 v1 = *(const float4*)&KVs[c * 64 + tx * 8 + 4];
            float vv[8] = {v0.x, v0.y, v0.z, v0.w, v1.x, v1.y, v1.z, v1.w};
#pragma unroll
            for (int j = 0; j < 8; j++) { o0[j] += p0 * vv[j]; o1[j] += p1 * vv[j]; }
        }
        __syncthreads();
    }

    float r0 = 1.f / l0, r1 = 1.f / l1;
    float* Og = Om + (size_t)(b * Ss + q0) * Dd + h * DKh;
    float4 w;
    w.x = o0[0] * r0; w.y = o0[1] * r0; w.z = o0[2] * r0; w.w = o0[3] * r0;
    *(float4*)(Og + (size_t)ty * Dd + tx * 8) = w;
    w.x = o0[4] * r0; w.y = o0[5] * r0; w.z = o0[6] * r0; w.w = o0[7] * r0;
    *(float4*)(Og + (size_t)ty * Dd + tx * 8 + 4) = w;
    w.x = o1[0] * r1; w.y = o1[1] * r1; w.z = o1[2] * r1; w.w = o1[3] * r1;
    *(float4*)(Og + (size_t)(ty + 32) * Dd + tx * 8) = w;
    w.x = o1[4] * r1; w.y = o1[5] * r1; w.z = o1[6] * r1; w.w = o1[7] * r1;
    *(float4*)(Og + (size_t)(ty + 32) * Dd + tx * 8 + 4) = w;
}

// ---------------------------------------------------------------------------
extern "C" void kernel_launch(void* const* d_in, const int* in_sizes, int n_in,
                              void* d_out, int out_size)
{
    const float* x  = (const float*)d_in[0];
    const float* Wq = (const float*)d_in[1];
    const float* bq = (const float*)d_in[2];
    const float* Wk = (const float*)d_in[3];
    const float* bk = (const float*)d_in[4];
    const float* Wv = (const float*)d_in[5];
    const float* bv = (const float*)d_in[6];
    const float* Wo = (const float*)d_in[7];
    const float* bo = (const float*)d_in[8];
    float* out = (float*)d_out;

    float *q, *k, *v, *o, *wt;
    cudaGetSymbolAddress((void**)&q, g_q);
    cudaGetSymbolAddress((void**)&k, g_k);
    cudaGetSymbolAddress((void**)&v, g_v);
    cudaGetSymbolAddress((void**)&o, g_o);
    cudaGetSymbolAddress((void**)&wt, g_wt);

    cudaFuncSetAttribute(gemm_bf16x3, cudaFuncAttributeMaxDynamicSharedMemorySize, SMTOT);

    dim3 tGrid(32, 32);
    transpose_w<<<tGrid, 256>>>(Wq, wt + 0u * Dd * Dd);
    transpose_w<<<tGrid, 256>>>(Wk, wt + 1u * Dd * Dd);
    transpose_w<<<tGrid, 256>>>(Wv, wt + 2u * Dd * Dd);
    transpose_w<<<tGrid, 256>>>(Wo, wt + 3u * Dd * Dd);

    dim3 gGrid(Dd / 128, Mtot / 128);   // (8, 32)
    gemm_bf16x3<<<gGrid, 256, SMTOT>>>(x, wt + 0u * Dd * Dd, bq, q, 0.125f);
    gemm_bf16x3<<<gGrid, 256, SMTOT>>>(x, wt + 1u * Dd * Dd, bk, k, 1.0f);
    gemm_bf16x3<<<gGrid, 256, SMTOT>>>(x, wt + 2u * Dd * Dd, bv, v, 1.0f);

    attn_kernel<<<dim3(Bb * Hh, Ss / BQ), 256>>>(q, k, v, o);

    gemm_bf16x3<<<gGrid, 256, SMTOT>>>(o, wt + 3u * Dd * Dd, bo, out, 1.0f);
}

// round 5
// speedup vs baseline: 4.6351x; 3.8999x over previous
#include <cuda_runtime.h>
#include <cuda_bf16.h>
#include <cstdint>

#define Bb   2
#define Ss   2048
#define Dd   1024
#define Hh   16
#define DKh  64
#define Mtot (Bb * Ss)

__device__ float g_q[Mtot * Dd];
__device__ float g_k[Mtot * Dd];
__device__ float g_v[Mtot * Dd];
__device__ float g_o[Mtot * Dd];
__device__ float g_wt[4u * Dd * Dd];

// ---------------- helpers ----------------
__device__ __forceinline__ uint32_t smem_u32(const void* p) {
    uint32_t a;
    asm("{ .reg .u64 t; cvta.to.shared.u64 t, %1; cvt.u32.u64 %0, t; }" : "=r"(a) : "l"(p));
    return a;
}
__device__ __forceinline__ void mma_bf16(float* c, const uint32_t* a, uint32_t b0, uint32_t b1)
{
    asm volatile(
        "mma.sync.aligned.m16n8k16.row.col.f32.bf16.bf16.f32 "
        "{%0,%1,%2,%3},{%4,%5,%6,%7},{%8,%9},{%0,%1,%2,%3};"
        : "+f"(c[0]), "+f"(c[1]), "+f"(c[2]), "+f"(c[3])
        : "r"(a[0]), "r"(a[1]), "r"(a[2]), "r"(a[3]), "r"(b0), "r"(b1));
}
__device__ __forceinline__ void ldmx4t(uint32_t* r, uint32_t addr)
{
    asm volatile("ldmatrix.sync.aligned.m8n8.x4.trans.shared.b16 {%0,%1,%2,%3}, [%4];"
        : "=r"(r[0]), "=r"(r[1]), "=r"(r[2]), "=r"(r[3]) : "r"(addr));
}
__device__ __forceinline__ void split_sts(__nv_bfloat16* hiP, __nv_bfloat16* loP, float4 a)
{
    __nv_bfloat162 h0 = __float22bfloat162_rn(make_float2(a.x, a.y));
    __nv_bfloat162 h1 = __float22bfloat162_rn(make_float2(a.z, a.w));
    float2 f0 = __bfloat1622float2(h0), f1 = __bfloat1622float2(h1);
    __nv_bfloat162 l0 = __float22bfloat162_rn(make_float2(a.x - f0.x, a.y - f0.y));
    __nv_bfloat162 l1 = __float22bfloat162_rn(make_float2(a.z - f1.x, a.w - f1.y));
    *(uint2*)hiP = make_uint2(*(uint32_t*)&h0, *(uint32_t*)&h1);
    *(uint2*)loP = make_uint2(*(uint32_t*)&l0, *(uint32_t*)&l1);
}
__device__ __forceinline__ void packhl(float a, float b, uint32_t& hi, uint32_t& lo)
{
    __nv_bfloat162 h = __float22bfloat162_rn(make_float2(a, b));
    float2 hf = __bfloat1622float2(h);
    __nv_bfloat162 l = __float22bfloat162_rn(make_float2(a - hf.x, b - hf.y));
    hi = *(uint32_t*)&h; lo = *(uint32_t*)&l;
}

// ---------------------------------------------------------------------------
// Weight transpose
// ---------------------------------------------------------------------------
__global__ __launch_bounds__(256) void transpose_w(const float* __restrict__ W, float* __restrict__ Wt)
{
    __shared__ float tile[32][33];
    int bx = blockIdx.x * 32, by = blockIdx.y * 32;
    int tx = threadIdx.x & 31, ty8 = threadIdx.x >> 5;
#pragma unroll
    for (int i = 0; i < 4; i++)
        tile[ty8 + i * 8][tx] = W[(size_t)(by + ty8 + i * 8) * Dd + bx + tx];
    __syncthreads();
#pragma unroll
    for (int i = 0; i < 4; i++)
        Wt[(size_t)(bx + ty8 + i * 8) * Dd + by + tx] = tile[tx][ty8 + i * 8];
}

// ---------------------------------------------------------------------------
// 3xBF16 mma GEMM (unchanged from R4)
// ---------------------------------------------------------------------------
#define RS   40
#define TILEB (128 * RS * 2)
#define SBUF  (4 * TILEB)
#define SMTOT (2 * SBUF)

__global__ __launch_bounds__(256, 1) void gemm_bf16x3(
    const float* __restrict__ A, const float* __restrict__ Wt,
    const float* __restrict__ bias, float* __restrict__ C, float scale)
{
    extern __shared__ __align__(16) char smem[];
    const int t = threadIdx.x, l = t & 31, wid = t >> 5;
    const int wm = wid >> 1, wn = wid & 1;
    const int row0 = blockIdx.y * 128, col0 = blockIdx.x * 128;
    const int lr = l >> 2, lc = (l & 3) * 2;

    float acc[2][8][4];
#pragma unroll
    for (int mt = 0; mt < 2; mt++)
#pragma unroll
        for (int nt = 0; nt < 8; nt++)
#pragma unroll
            for (int j = 0; j < 4; j++) acc[mt][nt][j] = 0.f;

    float4 av[4], bv[4];
#pragma unroll
    for (int i = 0; i < 4; i++) {
        int f = t + i * 256, r = f >> 3, q = f & 7;
        av[i] = *(const float4*)(A  + (size_t)(row0 + r) * Dd + q * 4);
        bv[i] = *(const float4*)(Wt + (size_t)(col0 + r) * Dd + q * 4);
    }
#pragma unroll
    for (int i = 0; i < 4; i++) {
        int f = t + i * 256, r = f >> 3, q = f & 7;
        __nv_bfloat16* base = (__nv_bfloat16*)smem;
        split_sts(base + 0 * (TILEB / 2) + r * RS + q * 4,
                  base + 1 * (TILEB / 2) + r * RS + q * 4, av[i]);
        split_sts(base + 2 * (TILEB / 2) + r * RS + q * 4,
                  base + 3 * (TILEB / 2) + r * RS + q * 4, bv[i]);
    }
    __syncthreads();

    for (int ch = 0; ch < 32; ch++) {
        const int cur = ch & 1;
        if (ch < 31) {
            const int k0 = (ch + 1) * 32;
#pragma unroll
            for (int i = 0; i < 4; i++) {
                int f = t + i * 256, r = f >> 3, q = f & 7;
                av[i] = *(const float4*)(A  + (size_t)(row0 + r) * Dd + k0 + q * 4);
                bv[i] = *(const float4*)(Wt + (size_t)(col0 + r) * Dd + k0 + q * 4);
            }
        }
        const __nv_bfloat16* Ah = (const __nv_bfloat16*)(smem + cur * SBUF);
        const __nv_bfloat16* Al = Ah + TILEB / 2;
        const __nv_bfloat16* Bh = Al + TILEB / 2;
        const __nv_bfloat16* Bl = Bh + TILEB / 2;

#pragma unroll
        for (int kk = 0; kk < 2; kk++) {
            const int kb = kk * 16 + lc;
            uint32_t ah[2][4], al[2][4];
#pragma unroll
            for (int mt = 0; mt < 2; mt++) {
                int r = wm * 32 + mt * 16 + lr;
                ah[mt][0] = *(const uint32_t*)&Ah[r * RS + kb];
                ah[mt][1] = *(const uint32_t*)&Ah[(r + 8) * RS + kb];
                ah[mt][2] = *(const uint32_t*)&Ah[r * RS + kb + 8];
                ah[mt][3] = *(const uint32_t*)&Ah[(r + 8) * RS + kb + 8];
                al[mt][0] = *(const uint32_t*)&Al[r * RS + kb];
                al[mt][1] = *(const uint32_t*)&Al[(r + 8) * RS + kb];
                al[mt][2] = *(const uint32_t*)&Al[r * RS + kb + 8];
                al[mt][3] = *(const uint32_t*)&Al[(r + 8) * RS + kb + 8];
            }
#pragma unroll
            for (int nt = 0; nt < 8; nt++) {
                int rn = wn * 64 + nt * 8 + lr;
                uint32_t bh0 = *(const uint32_t*)&Bh[rn * RS + kb];
                uint32_t bh1 = *(const uint32_t*)&Bh[rn * RS + kb + 8];
                uint32_t bl0 = *(const uint32_t*)&Bl[rn * RS + kb];
                uint32_t bl1 = *(const uint32_t*)&Bl[rn * RS + kb + 8];
#pragma unroll
                for (int mt = 0; mt < 2; mt++) {
                    mma_bf16(acc[mt][nt], ah[mt], bh0, bh1);
                    mma_bf16(acc[mt][nt], ah[mt], bl0, bl1);
                    mma_bf16(acc[mt][nt], al[mt], bh0, bh1);
                }
            }
        }

        if (ch < 31) {
            const int nxt = 1 - cur;
            __nv_bfloat16* base = (__nv_bfloat16*)(smem + nxt * SBUF);
#pragma unroll
            for (int i = 0; i < 4; i++) {
                int f = t + i * 256, r = f >> 3, q = f & 7;
                split_sts(base + 0 * (TILEB / 2) + r * RS + q * 4,
                          base + 1 * (TILEB / 2) + r * RS + q * 4, av[i]);
                split_sts(base + 2 * (TILEB / 2) + r * RS + q * 4,
                          base + 3 * (TILEB / 2) + r * RS + q * 4, bv[i]);
            }
        }
        __syncthreads();
    }

#pragma unroll
    for (int mt = 0; mt < 2; mt++) {
        const int r0 = row0 + wm * 32 + mt * 16 + lr;
#pragma unroll
        for (int nt = 0; nt < 8; nt++) {
            const int c = col0 + wn * 64 + nt * 8 + lc;
            float2 bb = *(const float2*)&bias[c];
            float2 v0 = make_float2((acc[mt][nt][0] + bb.x) * scale,
                                    (acc[mt][nt][1] + bb.y) * scale);
            float2 v1 = make_float2((acc[mt][nt][2] + bb.x) * scale,
                                    (acc[mt][nt][3] + bb.y) * scale);
            *(float2*)(C + (size_t)r0 * Dd + c)       = v0;
            *(float2*)(C + (size_t)(r0 + 8) * Dd + c) = v1;
        }
    }
}

// ---------------------------------------------------------------------------
// Flash attention with 3xBF16 mma.sync.
// Block = (b,h) x 128-query tile. 8 warps x 16 rows. 64 keys/iter. DK=64.
// SMEM (bf16, stride 72): Qh,Ql[128x72] Kh,Kl[64x72] Vh,Vl[64x72] = 73728 B.
// ---------------------------------------------------------------------------
#define ARS 72
#define SQH 0
#define SQL (128 * ARS)
#define SKH (SQL + 128 * ARS)
#define SKL (SKH + 64 * ARS)
#define SVH (SKL + 64 * ARS)
#define SVL (SVH + 64 * ARS)
#define ASMEM ((SVL + 64 * ARS) * 2)

__global__ __launch_bounds__(256, 1) void attn_mma(
    const float* __restrict__ Qm, const float* __restrict__ Km,
    const float* __restrict__ Vm, float* __restrict__ Om)
{
    extern __shared__ __align__(16) __nv_bfloat16 sm[];
    const int t = threadIdx.x, l = t & 31, wid = t >> 5;
    const int lr = l >> 2, lc = l & 3;
    const int b = blockIdx.x >> 4, h = blockIdx.x & 15;
    const int q0 = blockIdx.y * 128;
    const int hc = h * DKh;
    const int wrow = wid * 16;

    // Load + split Q tile (128x64) once
    const float* Qg = Qm + (size_t)(b * Ss + q0) * Dd + hc;
#pragma unroll
    for (int i = 0; i < 8; i++) {
        int f = t + i * 256, r = f >> 4, q = f & 15;
        float4 v = *(const float4*)(Qg + (size_t)r * Dd + q * 4);
        split_sts(sm + SQH + r * ARS + q * 4, sm + SQL + r * ARS + q * 4, v);
    }
    __syncthreads();

    // Q fragments in registers (persist for whole block)
    uint32_t qh[4][4], ql[4][4];
#pragma unroll
    for (int kc = 0; kc < 4; kc++)
#pragma unroll
        for (int j = 0; j < 4; j++) {
            int rr = wrow + lr + (j & 1) * 8;
            int cc = kc * 16 + (j >> 1) * 8 + lc * 2;
            qh[kc][j] = *(const uint32_t*)&sm[SQH + rr * ARS + cc];
            ql[kc][j] = *(const uint32_t*)&sm[SQL + rr * ARS + cc];
        }

    float m0 = -INFINITY, m1 = -INFINITY, lsum0 = 0.f, lsum1 = 0.f;
    float o[8][4];
#pragma unroll
    for (int nt = 0; nt < 8; nt++)
#pragma unroll
        for (int j = 0; j < 4; j++) o[nt][j] = 0.f;

    const float* Kg = Km + (size_t)(b * Ss) * Dd + hc;
    const float* Vg = Vm + (size_t)(b * Ss) * Dd + hc;
    const uint32_t vh32 = smem_u32(sm + SVH), vl32 = smem_u32(sm + SVL);
    const int vkey = (l & 15), vdks = (l >> 4) * 8;

    for (int kt = 0; kt < Ss; kt += 64) {
        // load + split K,V tiles (64x64 each)
#pragma unroll
        for (int i = 0; i < 4; i++) {
            int f = t + i * 256, r = f >> 4, q = f & 15;
            float4 kv = *(const float4*)(Kg + (size_t)(kt + r) * Dd + q * 4);
            split_sts(sm + SKH + r * ARS + q * 4, sm + SKL + r * ARS + q * 4, kv);
            float4 vv = *(const float4*)(Vg + (size_t)(kt + r) * Dd + q * 4);
            split_sts(sm + SVH + r * ARS + q * 4, sm + SVL + r * ARS + q * 4, vv);
        }
        __syncthreads();

        // S = Q @ K^T  (3xBF16)
        float s[8][4];
#pragma unroll
        for (int nt = 0; nt < 8; nt++) {
            s[nt][0] = s[nt][1] = s[nt][2] = s[nt][3] = 0.f;
#pragma unroll
            for (int kc = 0; kc < 4; kc++) {
                const __nv_bfloat16* kp = &sm[SKH + (nt * 8 + lr) * ARS + kc * 16 + lc * 2];
                const __nv_bfloat16* lp = &sm[SKL + (nt * 8 + lr) * ARS + kc * 16 + lc * 2];
                uint32_t bh0 = *(const uint32_t*)kp, bh1 = *(const uint32_t*)(kp + 8);
                uint32_t bl0 = *(const uint32_t*)lp, bl1 = *(const uint32_t*)(lp + 8);
                mma_bf16(s[nt], qh[kc], bh0, bh1);
                mma_bf16(s[nt], qh[kc], bl0, bl1);
                mma_bf16(s[nt], ql[kc], bh0, bh1);
            }
        }

        // online softmax (rows lr -> 0, lr+8 -> 1)
        float mx0 = s[0][0], mx1 = s[0][2];
#pragma unroll
        for (int nt = 0; nt < 8; nt++) {
            mx0 = fmaxf(mx0, fmaxf(s[nt][0], s[nt][1]));
            mx1 = fmaxf(mx1, fmaxf(s[nt][2], s[nt][3]));
        }
        mx0 = fmaxf(mx0, __shfl_xor_sync(0xffffffffu, mx0, 1));
        mx0 = fmaxf(mx0, __shfl_xor_sync(0xffffffffu, mx0, 2));
        mx1 = fmaxf(mx1, __shfl_xor_sync(0xffffffffu, mx1, 1));
        mx1 = fmaxf(mx1, __shfl_xor_sync(0xffffffffu, mx1, 2));
        float mn0 = fmaxf(m0, mx0), mn1 = fmaxf(m1, mx1);
        float c0 = __expf(m0 - mn0), c1 = __expf(m1 - mn1);
        m0 = mn0; m1 = mn1;

        float sum0 = 0.f, sum1 = 0.f;
#pragma unroll
        for (int nt = 0; nt < 8; nt++) {
            s[nt][0] = __expf(s[nt][0] - mn0);
            s[nt][1] = __expf(s[nt][1] - mn0);
            s[nt][2] = __expf(s[nt][2] - mn1);
            s[nt][3] = __expf(s[nt][3] - mn1);
            sum0 += s[nt][0] + s[nt][1];
            sum1 += s[nt][2] + s[nt][3];
        }
        sum0 += __shfl_xor_sync(0xffffffffu, sum0, 1);
        sum0 += __shfl_xor_sync(0xffffffffu, sum0, 2);
        sum1 += __shfl_xor_sync(0xffffffffu, sum1, 1);
        sum1 += __shfl_xor_sync(0xffffffffu, sum1, 2);
        lsum0 = lsum0 * c0 + sum0;
        lsum1 = lsum1 * c1 + sum1;
#pragma unroll
        for (int nt = 0; nt < 8; nt++) {
            o[nt][0] *= c0; o[nt][1] *= c0;
            o[nt][2] *= c1; o[nt][3] *= c1;
        }

        // repack P (registers only) into A fragments, hi/lo
        uint32_t ph[4][4], pl[4][4];
#pragma unroll
        for (int kc = 0; kc < 4; kc++) {
            packhl(s[2 * kc][0],     s[2 * kc][1],     ph[kc][0], pl[kc][0]);
            packhl(s[2 * kc][2],     s[2 * kc][3],     ph[kc][1], pl[kc][1]);
            packhl(s[2 * kc + 1][0], s[2 * kc + 1][1], ph[kc][2], pl[kc][2]);
            packhl(s[2 * kc + 1][2], s[2 * kc + 1][3], ph[kc][3], pl[kc][3]);
        }

        // O += P @ V  (V^T fragments via ldmatrix.trans)
#pragma unroll
        for (int kc = 0; kc < 4; kc++) {
            const uint32_t rowoff = ((kc * 16 + vkey) * ARS + vdks) * 2;
#pragma unroll
            for (int np = 0; np < 4; np++) {
                uint32_t rh[4], rl[4];
                ldmx4t(rh, vh32 + rowoff + np * 32);
                ldmx4t(rl, vl32 + rowoff + np * 32);
                mma_bf16(o[2 * np],     ph[kc], rh[0], rh[1]);
                mma_bf16(o[2 * np],     ph[kc], rl[0], rl[1]);
                mma_bf16(o[2 * np],     pl[kc], rh[0], rh[1]);
                mma_bf16(o[2 * np + 1], ph[kc], rh[2], rh[3]);
                mma_bf16(o[2 * np + 1], ph[kc], rl[2], rl[3]);
                mma_bf16(o[2 * np + 1], pl[kc], rh[2], rh[3]);
            }
        }
        __syncthreads();
    }

    // finalize
    float i0 = 1.f / lsum0, i1 = 1.f / lsum1;
    float* Og = Om + (size_t)(b * Ss + q0 + wrow) * Dd + hc;
#pragma unroll
    for (int nt = 0; nt < 8; nt++) {
        *(float2*)(Og + (size_t)lr * Dd + nt * 8 + lc * 2) =
            make_float2(o[nt][0] * i0, o[nt][1] * i0);
        *(float2*)(Og + (size_t)(lr + 8) * Dd + nt * 8 + lc * 2) =
            make_float2(o[nt][2] * i1, o[nt][3] * i1);
    }
}

// ---------------------------------------------------------------------------
extern "C" void kernel_launch(void* const* d_in, const int* in_sizes, int n_in,
                              void* d_out, int out_size)
{
    const float* x  = (const float*)d_in[0];
    const float* Wq = (const float*)d_in[1];
    const float* bq = (const float*)d_in[2];
    const float* Wk = (const float*)d_in[3];
    const float* bk = (const float*)d_in[4];
    const float* Wv = (const float*)d_in[5];
    const float* bv = (const float*)d_in[6];
    const float* Wo = (const float*)d_in[7];
    const float* bo = (const float*)d_in[8];
    float* out = (float*)d_out;

    float *q, *k, *v, *o, *wt;
    cudaGetSymbolAddress((void**)&q, g_q);
    cudaGetSymbolAddress((void**)&k, g_k);
    cudaGetSymbolAddress((void**)&v, g_v);
    cudaGetSymbolAddress((void**)&o, g_o);
    cudaGetSymbolAddress((void**)&wt, g_wt);

    cudaFuncSetAttribute(gemm_bf16x3, cudaFuncAttributeMaxDynamicSharedMemorySize, SMTOT);
    cudaFuncSetAttribute(attn_mma, cudaFuncAttributeMaxDynamicSharedMemorySize, ASMEM);

    dim3 tGrid(32, 32);
    transpose_w<<<tGrid, 256>>>(Wq, wt + 0u * Dd * Dd);
    transpose_w<<<tGrid, 256>>>(Wk, wt + 1u * Dd * Dd);
    transpose_w<<<tGrid, 256>>>(Wv, wt + 2u * Dd * Dd);
    transpose_w<<<tGrid, 256>>>(Wo, wt + 3u * Dd * Dd);

    dim3 gGrid(Dd / 128, Mtot / 128);
    gemm_bf16x3<<<gGrid, 256, SMTOT>>>(x, wt + 0u * Dd * Dd, bq, q, 0.125f);
    gemm_bf16x3<<<gGrid, 256, SMTOT>>>(x, wt + 1u * Dd * Dd, bk, k, 1.0f);
    gemm_bf16x3<<<gGrid, 256, SMTOT>>>(x, wt + 2u * Dd * Dd, bv, v, 1.0f);

    attn_mma<<<dim3(Bb * Hh, Ss / 128), 256, ASMEM>>>(q, k, v, o);

    gemm_bf16x3<<<gGrid, 256, SMTOT>>>(o, wt + 3u * Dd * Dd, bo, out, 1.0f);
}

// round 6
// speedup vs baseline: 4.9240x; 1.0623x over previous
#include <cuda_runtime.h>
#include <cuda_bf16.h>
#include <cstdint>

#define Bb   2
#define Ss   2048
#define Dd   1024
#define Hh   16
#define DKh  64
#define Mtot (Bb * Ss)

typedef __nv_bfloat16 bf16;

// pre-split bf16 hi/lo buffers (device globals; no allocations allowed)
__device__ bf16 g_xh[Mtot * Dd], g_xl[Mtot * Dd];
__device__ bf16 g_wth[4u * Dd * Dd], g_wtl[4u * Dd * Dd];
__device__ bf16 g_qh[Mtot * Dd], g_ql[Mtot * Dd];
__device__ bf16 g_kh[Mtot * Dd], g_kl[Mtot * Dd];
__device__ bf16 g_vh[Mtot * Dd], g_vl[Mtot * Dd];
__device__ bf16 g_oh[Mtot * Dd], g_ol[Mtot * Dd];

// ---------------- PTX helpers ----------------
__device__ __forceinline__ uint32_t smem_u32(const void* p) {
    uint32_t a;
    asm("{ .reg .u64 t; cvta.to.shared.u64 t, %1; cvt.u32.u64 %0, t; }" : "=r"(a) : "l"(p));
    return a;
}
__device__ __forceinline__ void cpa16(uint32_t dst, const void* src) {
    asm volatile("cp.async.ca.shared.global [%0], [%1], 16;" :: "r"(dst), "l"(src));
}
#define CP_COMMIT() asm volatile("cp.async.commit_group;" ::: "memory")
#define CP_WAIT(n)  asm volatile("cp.async.wait_group %0;" :: "n"(n) : "memory")

__device__ __forceinline__ void mma_bf16(float* c, const uint32_t* a, uint32_t b0, uint32_t b1)
{
    asm volatile(
        "mma.sync.aligned.m16n8k16.row.col.f32.bf16.bf16.f32 "
        "{%0,%1,%2,%3},{%4,%5,%6,%7},{%8,%9},{%0,%1,%2,%3};"
        : "+f"(c[0]), "+f"(c[1]), "+f"(c[2]), "+f"(c[3])
        : "r"(a[0]), "r"(a[1]), "r"(a[2]), "r"(a[3]), "r"(b0), "r"(b1));
}
__device__ __forceinline__ void ldmx4t(uint32_t* r, uint32_t addr)
{
    asm volatile("ldmatrix.sync.aligned.m8n8.x4.trans.shared.b16 {%0,%1,%2,%3}, [%4];"
        : "=r"(r[0]), "=r"(r[1]), "=r"(r[2]), "=r"(r[3]) : "r"(addr));
}
__device__ __forceinline__ void packhl(float a, float b, uint32_t& hi, uint32_t& lo)
{
    __nv_bfloat162 h = __float22bfloat162_rn(make_float2(a, b));
    float2 hf = __bfloat1622float2(h);
    __nv_bfloat162 l = __float22bfloat162_rn(make_float2(a - hf.x, b - hf.y));
    hi = *(uint32_t*)&h; lo = *(uint32_t*)&l;
}

// ---------------------------------------------------------------------------
// Prep: split x (fp32 -> bf16 hi/lo), and split+transpose weights.
// ---------------------------------------------------------------------------
__global__ __launch_bounds__(256) void split_x(const float* __restrict__ X,
                                               bf16* __restrict__ Xh, bf16* __restrict__ Xl)
{
    int i = blockIdx.x * 256 + threadIdx.x;     // over float4s, total 1048576
    float4 v = ((const float4*)X)[i];
    uint32_t h0, l0, h1, l1;
    packhl(v.x, v.y, h0, l0);
    packhl(v.z, v.w, h1, l1);
    ((uint2*)Xh)[i] = make_uint2(h0, h1);
    ((uint2*)Xl)[i] = make_uint2(l0, l1);
}

__global__ __launch_bounds__(256) void split_wt(const float* __restrict__ W,
                                                bf16* __restrict__ Wth, bf16* __restrict__ Wtl)
{
    __shared__ float tile[32][33];
    int bx = blockIdx.x * 32, by = blockIdx.y * 32;
    int tx = threadIdx.x & 31, ty8 = threadIdx.x >> 5;
#pragma unroll
    for (int i = 0; i < 4; i++)
        tile[ty8 + i * 8][tx] = W[(size_t)(by + ty8 + i * 8) * Dd + bx + tx];
    __syncthreads();
#pragma unroll
    for (int i = 0; i < 4; i++) {
        float v = tile[tx][ty8 + i * 8];
        bf16 h = __float2bfloat16_rn(v);
        bf16 lo = __float2bfloat16_rn(v - __bfloat162float(h));
        size_t idx = (size_t)(bx + ty8 + i * 8) * Dd + by + tx;
        Wth[idx] = h; Wtl[idx] = lo;
    }
}

// ---------------------------------------------------------------------------
// 3xBF16 GEMM, pre-split inputs. C = (A @ Wt^T + bias) * scale.
// CTA 128x128, 128 thr (4 warps 2x2), warp tile 64x64, BK=32, cp.async x2 buf.
// ---------------------------------------------------------------------------
#define GRS  40
#define GT_AL (128 * GRS)
#define GT_B  (2 * 128 * GRS)
#define GT_BL (3 * 128 * GRS)
#define GBUF  (4 * 128 * GRS)     // elems per buffer
#define GSM   (2 * GBUF * 2)      // bytes = 81920

template<int SPLIT>
__global__ __launch_bounds__(128, 2) void gemm_bfhl(
    const bf16* __restrict__ Ah, const bf16* __restrict__ Al,
    const bf16* __restrict__ Bh, const bf16* __restrict__ Bl,
    const float* __restrict__ bias, float scale,
    float* __restrict__ C, bf16* __restrict__ Ch, bf16* __restrict__ Cl)
{
    extern __shared__ __align__(16) bf16 sm[];
    const int t = threadIdx.x, l = t & 31, wid = t >> 5;
    const int wm = wid >> 1, wn = wid & 1;
    const int row0 = blockIdx.y * 128, col0 = blockIdx.x * 128;
    const int lr = l >> 2, lc2 = (l & 3) * 2;
    const uint32_t sb = smem_u32(sm);

    float acc[4][8][4];
#pragma unroll
    for (int mt = 0; mt < 4; mt++)
#pragma unroll
        for (int nt = 0; nt < 8; nt++)
#pragma unroll
            for (int j = 0; j < 4; j++) acc[mt][nt][j] = 0.f;

    const int gr = t >> 2, gc8 = (t & 3) * 8;   // granule row/col within tile

    // chunk loader: 16 cp.async per thread
    auto load = [&](int ch, int buf) {
        const int k0 = ch * 32;
        const uint32_t base = sb + buf * GBUF * 2;
#pragma unroll
        for (int i = 0; i < 4; i++) {
            int r = gr + i * 32;
            uint32_t doff = (r * GRS + gc8) * 2;
            cpa16(base + doff,             Ah + (size_t)(row0 + r) * Dd + k0 + gc8);
            cpa16(base + GT_AL * 2 + doff, Al + (size_t)(row0 + r) * Dd + k0 + gc8);
            cpa16(base + GT_B * 2 + doff,  Bh + (size_t)(col0 + r) * Dd + k0 + gc8);
            cpa16(base + GT_BL * 2 + doff, Bl + (size_t)(col0 + r) * Dd + k0 + gc8);
        }
    };

    load(0, 0); CP_COMMIT();

    for (int ch = 0; ch < 32; ch++) {
        if (ch < 31) { load(ch + 1, (ch + 1) & 1); CP_COMMIT(); CP_WAIT(1); }
        else CP_WAIT(0);
        __syncthreads();

        const bf16* pA  = sm + (ch & 1) * GBUF;
        const bf16* pAl = pA + GT_AL;
        const bf16* pB  = pA + GT_B;
        const bf16* pBl = pA + GT_BL;

#pragma unroll
        for (int kk = 0; kk < 2; kk++) {
            const int kb = kk * 16 + lc2;
            uint32_t ahf[4][4], alf[4][4];
#pragma unroll
            for (int mt = 0; mt < 4; mt++) {
                int r = wm * 64 + mt * 16 + lr;
                ahf[mt][0] = *(const uint32_t*)&pA[r * GRS + kb];
                ahf[mt][1] = *(const uint32_t*)&pA[(r + 8) * GRS + kb];
                ahf[mt][2] = *(const uint32_t*)&pA[r * GRS + kb + 8];
                ahf[mt][3] = *(const uint32_t*)&pA[(r + 8) * GRS + kb + 8];
                alf[mt][0] = *(const uint32_t*)&pAl[r * GRS + kb];
                alf[mt][1] = *(const uint32_t*)&pAl[(r + 8) * GRS + kb];
                alf[mt][2] = *(const uint32_t*)&pAl[r * GRS + kb + 8];
                alf[mt][3] = *(const uint32_t*)&pAl[(r + 8) * GRS + kb + 8];
            }
#pragma unroll
            for (int nt = 0; nt < 8; nt++) {
                int rn = wn * 64 + nt * 8 + lr;
                uint32_t bh0 = *(const uint32_t*)&pB[rn * GRS + kb];
                uint32_t bh1 = *(const uint32_t*)&pB[rn * GRS + kb + 8];
                uint32_t bl0 = *(const uint32_t*)&pBl[rn * GRS + kb];
                uint32_t bl1 = *(const uint32_t*)&pBl[rn * GRS + kb + 8];
#pragma unroll
                for (int mt = 0; mt < 4; mt++) {
                    mma_bf16(acc[mt][nt], ahf[mt], bh0, bh1);
                    mma_bf16(acc[mt][nt], ahf[mt], bl0, bl1);
                    mma_bf16(acc[mt][nt], alf[mt], bh0, bh1);
                }
            }
        }
        __syncthreads();
    }

#pragma unroll
    for (int mt = 0; mt < 4; mt++) {
        const int r = row0 + wm * 64 + mt * 16 + lr;
#pragma unroll
        for (int nt = 0; nt < 8; nt++) {
            const int c = col0 + wn * 64 + nt * 8 + lc2;
            float2 bb = *(const float2*)&bias[c];
            float p0 = (acc[mt][nt][0] + bb.x) * scale;
            float p1 = (acc[mt][nt][1] + bb.y) * scale;
            float p2 = (acc[mt][nt][2] + bb.x) * scale;
            float p3 = (acc[mt][nt][3] + bb.y) * scale;
            if (SPLIT) {
                uint32_t hi, lo;
                packhl(p0, p1, hi, lo);
                *(uint32_t*)&Ch[(size_t)r * Dd + c] = hi;
                *(uint32_t*)&Cl[(size_t)r * Dd + c] = lo;
                packhl(p2, p3, hi, lo);
                *(uint32_t*)&Ch[(size_t)(r + 8) * Dd + c] = hi;
                *(uint32_t*)&Cl[(size_t)(r + 8) * Dd + c] = lo;
            } else {
                *(float2*)(C + (size_t)r * Dd + c)       = make_float2(p0, p1);
                *(float2*)(C + (size_t)(r + 8) * Dd + c) = make_float2(p2, p3);
            }
        }
    }
}

// ---------------------------------------------------------------------------
// Flash attention, pre-split bf16 I/O.
// CTA = (b,h) x 256-query tile; 8 warps x 32 rows (mt=2 x 16). 64 keys/chunk.
// smem: Qh,Ql [256x72]; 2 x {Kh,Kl,Vh,Vl}[64x72]. cp.async double buffer.
// ---------------------------------------------------------------------------
#define ARS 72
#define AQL (256 * ARS)
#define AKV0 (2 * 256 * ARS)
#define KVB (4 * 64 * ARS)          // elems per KV buffer = 18432
#define ASMB ((2 * 256 * ARS + 2 * KVB) * 2)   // 147456 bytes

__global__ __launch_bounds__(256, 1) void attn_bfhl(
    const bf16* __restrict__ Qh, const bf16* __restrict__ Ql,
    const bf16* __restrict__ Kh, const bf16* __restrict__ Kl,
    const bf16* __restrict__ Vh, const bf16* __restrict__ Vl,
    bf16* __restrict__ Oh, bf16* __restrict__ Ol)
{
    extern __shared__ __align__(16) bf16 sm[];
    const int t = threadIdx.x, l = t & 31, wid = t >> 5;
    const int lr = l >> 2, lc2 = (l & 3) * 2;
    const int b = blockIdx.x >> 4, h = blockIdx.x & 15, hc = h * DKh;
    const int q0 = blockIdx.y * 256, wrow = wid * 32;
    const uint32_t sb = smem_u32(sm);
    const int vkey = l & 15, vdks = (l >> 4) * 8;

    const size_t qoff = (size_t)(b * Ss + q0) * Dd + hc;
    const size_t kvrow0 = (size_t)(b * Ss) * Dd + hc;

    // Q tiles: 16 granules per thread
    {
        const int r = t >> 3, c8 = (t & 7) * 8;
#pragma unroll
        for (int i = 0; i < 8; i++) {
            int rr = r + i * 32;
            uint32_t doff = (rr * ARS + c8) * 2;
            cpa16(sb + doff,           Qh + qoff + (size_t)rr * Dd + c8);
            cpa16(sb + AQL * 2 + doff, Ql + qoff + (size_t)rr * Dd + c8);
        }
    }
    CP_COMMIT();

    auto loadKV = [&](int ck, int buf) {
        const size_t koff = kvrow0 + (size_t)ck * 64 * Dd;
        const uint32_t base = sb + (AKV0 + buf * KVB) * 2;
        const int r = t >> 3, c8 = (t & 7) * 8;
#pragma unroll
        for (int i = 0; i < 2; i++) {
            int rr = r + i * 32;
            uint32_t doff = (rr * ARS + c8) * 2;
            const size_t goff = koff + (size_t)rr * Dd + c8;
            cpa16(base + doff,                    Kh + goff);
            cpa16(base + 1 * 64 * ARS * 2 + doff, Kl + goff);
            cpa16(base + 2 * 64 * ARS * 2 + doff, Vh + goff);
            cpa16(base + 3 * 64 * ARS * 2 + doff, Vl + goff);
        }
    };
    loadKV(0, 0); CP_COMMIT();
    loadKV(1, 1); CP_COMMIT();
    CP_WAIT(1);           // Q + KV0 complete
    __syncthreads();

    // Q fragments (persist): hi and lo
    uint32_t qhf[2][4][4], qlf[2][4][4];
#pragma unroll
    for (int mt = 0; mt < 2; mt++)
#pragma unroll
        for (int kc = 0; kc < 4; kc++)
#pragma unroll
            for (int j = 0; j < 4; j++) {
                int rr = wrow + mt * 16 + lr + (j & 1) * 8;
                int cc = kc * 16 + (j >> 1) * 8 + lc2;
                qhf[mt][kc][j] = *(const uint32_t*)&sm[rr * ARS + cc];
                qlf[mt][kc][j] = *(const uint32_t*)&sm[AQL + rr * ARS + cc];
            }

    float mrow[2][2], lrow[2][2];
    float o[2][8][4];
#pragma unroll
    for (int mt = 0; mt < 2; mt++) {
        mrow[mt][0] = mrow[mt][1] = -INFINITY;
        lrow[mt][0] = lrow[mt][1] = 0.f;
#pragma unroll
        for (int nt = 0; nt < 8; nt++)
#pragma unroll
            for (int j = 0; j < 4; j++) o[mt][nt][j] = 0.f;
    }

    for (int ck = 0; ck < 32; ck++) {
        const int buf = ck & 1;
        const bf16* pK  = sm + AKV0 + buf * KVB;
        const bf16* pKl = pK + 64 * ARS;
        const uint32_t vh32 = sb + (AKV0 + buf * KVB + 2 * 64 * ARS) * 2;
        const uint32_t vl32 = vh32 + 64 * ARS * 2;

        // S = Q K^T (3xBF16)
        float s[2][8][4];
#pragma unroll
        for (int mt = 0; mt < 2; mt++)
#pragma unroll
            for (int nt = 0; nt < 8; nt++)
                s[mt][nt][0] = s[mt][nt][1] = s[mt][nt][2] = s[mt][nt][3] = 0.f;
#pragma unroll
        for (int nt = 0; nt < 8; nt++) {
            const int rn = nt * 8 + lr;
#pragma unroll
            for (int kc = 0; kc < 4; kc++) {
                const int cb = kc * 16 + lc2;
                uint32_t bh0 = *(const uint32_t*)&pK[rn * ARS + cb];
                uint32_t bh1 = *(const uint32_t*)&pK[rn * ARS + cb + 8];
                uint32_t bl0 = *(const uint32_t*)&pKl[rn * ARS + cb];
                uint32_t bl1 = *(const uint32_t*)&pKl[rn * ARS + cb + 8];
#pragma unroll
                for (int mt = 0; mt < 2; mt++) {
                    mma_bf16(s[mt][nt], qhf[mt][kc], bh0, bh1);
                    mma_bf16(s[mt][nt], qhf[mt][kc], bl0, bl1);
                    mma_bf16(s[mt][nt], qlf[mt][kc], bh0, bh1);
                }
            }
        }

        // online softmax per mt
        float c01[2][2];
#pragma unroll
        for (int mt = 0; mt < 2; mt++) {
            float mx0 = s[mt][0][0], mx1 = s[mt][0][2];
#pragma unroll
            for (int nt = 0; nt < 8; nt++) {
                mx0 = fmaxf(mx0, fmaxf(s[mt][nt][0], s[mt][nt][1]));
                mx1 = fmaxf(mx1, fmaxf(s[mt][nt][2], s[mt][nt][3]));
            }
            mx0 = fmaxf(mx0, __shfl_xor_sync(0xffffffffu, mx0, 1));
            mx0 = fmaxf(mx0, __shfl_xor_sync(0xffffffffu, mx0, 2));
            mx1 = fmaxf(mx1, __shfl_xor_sync(0xffffffffu, mx1, 1));
            mx1 = fmaxf(mx1, __shfl_xor_sync(0xffffffffu, mx1, 2));
            float mn0 = fmaxf(mrow[mt][0], mx0), mn1 = fmaxf(mrow[mt][1], mx1);
            float c0 = __expf(mrow[mt][0] - mn0), c1 = __expf(mrow[mt][1] - mn1);
            mrow[mt][0] = mn0; mrow[mt][1] = mn1;
            float sum0 = 0.f, sum1 = 0.f;
#pragma unroll
            for (int nt = 0; nt < 8; nt++) {
                s[mt][nt][0] = __expf(s[mt][nt][0] - mn0);
                s[mt][nt][1] = __expf(s[mt][nt][1] - mn0);
                s[mt][nt][2] = __expf(s[mt][nt][2] - mn1);
                s[mt][nt][3] = __expf(s[mt][nt][3] - mn1);
                sum0 += s[mt][nt][0] + s[mt][nt][1];
                sum1 += s[mt][nt][2] + s[mt][nt][3];
            }
            sum0 += __shfl_xor_sync(0xffffffffu, sum0, 1);
            sum0 += __shfl_xor_sync(0xffffffffu, sum0, 2);
            sum1 += __shfl_xor_sync(0xffffffffu, sum1, 1);
            sum1 += __shfl_xor_sync(0xffffffffu, sum1, 2);
            lrow[mt][0] = lrow[mt][0] * c0 + sum0;
            lrow[mt][1] = lrow[mt][1] * c1 + sum1;
            c01[mt][0] = c0; c01[mt][1] = c1;
#pragma unroll
            for (int nt = 0; nt < 8; nt++) {
                o[mt][nt][0] *= c0; o[mt][nt][1] *= c0;
                o[mt][nt][2] *= c1; o[mt][nt][3] *= c1;
            }
        }

        // O += P V, per key 16-block: pack P then MMA against ldmatrix'd V^T
#pragma unroll
        for (int kc = 0; kc < 4; kc++) {
            uint32_t ph[2][4], pl[2][4];
#pragma unroll
            for (int mt = 0; mt < 2; mt++) {
                packhl(s[mt][2 * kc][0],     s[mt][2 * kc][1],     ph[mt][0], pl[mt][0]);
                packhl(s[mt][2 * kc][2],     s[mt][2 * kc][3],     ph[mt][1], pl[mt][1]);
                packhl(s[mt][2 * kc + 1][0], s[mt][2 * kc + 1][1], ph[mt][2], pl[mt][2]);
                packhl(s[mt][2 * kc + 1][2], s[mt][2 * kc + 1][3], ph[mt][3], pl[mt][3]);
            }
            const uint32_t rowoff = ((kc * 16 + vkey) * ARS + vdks) * 2;
#pragma unroll
            for (int np = 0; np < 4; np++) {
                uint32_t rh[4], rl[4];
                ldmx4t(rh, vh32 + rowoff + np * 32);
                ldmx4t(rl, vl32 + rowoff + np * 32);
#pragma unroll
                for (int mt = 0; mt < 2; mt++) {
                    mma_bf16(o[mt][2 * np],     ph[mt], rh[0], rh[1]);
                    mma_bf16(o[mt][2 * np],     ph[mt], rl[0], rl[1]);
                    mma_bf16(o[mt][2 * np],     pl[mt], rh[0], rh[1]);
                    mma_bf16(o[mt][2 * np + 1], ph[mt], rh[2], rh[3]);
                    mma_bf16(o[mt][2 * np + 1], ph[mt], rl[2], rl[3]);
                    mma_bf16(o[mt][2 * np + 1], pl[mt], rh[2], rh[3]);
                }
            }
        }

        __syncthreads();     // done reading this buffer
        if (ck + 2 < 32) { loadKV(ck + 2, buf); CP_COMMIT(); CP_WAIT(1); }
        else CP_WAIT(0);
        __syncthreads();     // next buffer visible to all
    }

    // finalize: normalize, split to bf16 hi/lo, store
#pragma unroll
    for (int mt = 0; mt < 2; mt++) {
        float i0 = 1.f / lrow[mt][0], i1 = 1.f / lrow[mt][1];
        const size_t r0 = (size_t)(b * Ss + q0 + wrow + mt * 16 + lr) * Dd + hc;
#pragma unroll
        for (int nt = 0; nt < 8; nt++) {
            uint32_t hi, lo;
            packhl(o[mt][nt][0] * i0, o[mt][nt][1] * i0, hi, lo);
            *(uint32_t*)&Oh[r0 + nt * 8 + lc2] = hi;
            *(uint32_t*)&Ol[r0 + nt * 8 + lc2] = lo;
            packhl(o[mt][nt][2] * i1, o[mt][nt][3] * i1, hi, lo);
            *(uint32_t*)&Oh[r0 + 8 * Dd + nt * 8 + lc2] = hi;
            *(uint32_t*)&Ol[r0 + 8 * Dd + nt * 8 + lc2] = lo;
        }
    }
}

// ---------------------------------------------------------------------------
extern "C" void kernel_launch(void* const* d_in, const int* in_sizes, int n_in,
                              void* d_out, int out_size)
{
    const float* x  = (const float*)d_in[0];
    const float* Wq = (const float*)d_in[1];
    const float* bq = (const float*)d_in[2];
    const float* Wk = (const float*)d_in[3];
    const float* bk = (const float*)d_in[4];
    const float* Wv = (const float*)d_in[5];
    const float* bv = (const float*)d_in[6];
    const float* Wo = (const float*)d_in[7];
    const float* bo = (const float*)d_in[8];
    float* out = (float*)d_out;

    bf16 *xh, *xl, *wth, *wtl, *qh, *ql, *kh, *kl, *vh, *vl, *oh, *ol;
    cudaGetSymbolAddress((void**)&xh, g_xh);  cudaGetSymbolAddress((void**)&xl, g_xl);
    cudaGetSymbolAddress((void**)&wth, g_wth); cudaGetSymbolAddress((void**)&wtl, g_wtl);
    cudaGetSymbolAddress((void**)&qh, g_qh);  cudaGetSymbolAddress((void**)&ql, g_ql);
    cudaGetSymbolAddress((void**)&kh, g_kh);  cudaGetSymbolAddress((void**)&kl, g_kl);
    cudaGetSymbolAddress((void**)&vh, g_vh);  cudaGetSymbolAddress((void**)&vl, g_vl);
    cudaGetSymbolAddress((void**)&oh, g_oh);  cudaGetSymbolAddress((void**)&ol, g_ol);

    cudaFuncSetAttribute(gemm_bfhl<0>, cudaFuncAttributeMaxDynamicSharedMemorySize, GSM);
    cudaFuncSetAttribute(gemm_bfhl<1>, cudaFuncAttributeMaxDynamicSharedMemorySize, GSM);
    cudaFuncSetAttribute(attn_bfhl,    cudaFuncAttributeMaxDynamicSharedMemorySize, ASMB);

    split_x<<<Mtot * Dd / 4 / 256, 256>>>(x, xh, xl);
    dim3 tGrid(32, 32);
    split_wt<<<tGrid, 256>>>(Wq, wth + 0u * Dd * Dd, wtl + 0u * Dd * Dd);
    split_wt<<<tGrid, 256>>>(Wk, wth + 1u * Dd * Dd, wtl + 1u * Dd * Dd);
    split_wt<<<tGrid, 256>>>(Wv, wth + 2u * Dd * Dd, wtl + 2u * Dd * Dd);
    split_wt<<<tGrid, 256>>>(Wo, wth + 3u * Dd * Dd, wtl + 3u * Dd * Dd);

    dim3 gGrid(Dd / 128, Mtot / 128);   // (8, 32)
    gemm_bfhl<1><<<gGrid, 128, GSM>>>(xh, xl, wth + 0u * Dd * Dd, wtl + 0u * Dd * Dd,
                                      bq, 0.125f, nullptr, qh, ql);
    gemm_bfhl<1><<<gGrid, 128, GSM>>>(xh, xl, wth + 1u * Dd * Dd, wtl + 1u * Dd * Dd,
                                      bk, 1.0f, nullptr, kh, kl);
    gemm_bfhl<1><<<gGrid, 128, GSM>>>(xh, xl, wth + 2u * Dd * Dd, wtl + 2u * Dd * Dd,
                                      bv, 1.0f, nullptr, vh, vl);

    attn_bfhl<<<dim3(Bb * Hh, Ss / 256), 256, ASMB>>>(qh, ql, kh, kl, vh, vl, oh, ol);

    gemm_bfhl<0><<<gGrid, 128, GSM>>>(oh, ol, wth + 3u * Dd * Dd, wtl + 3u * Dd * Dd,
                                      bo, 1.0f, out, nullptr, nullptr);
}

// round 7
// speedup vs baseline: 5.8319x; 1.1844x over previous
#include <cuda_runtime.h>
#include <cuda_bf16.h>
#include <cuda_fp16.h>
#include <cstdint>

#define Bb   2
#define Ss   2048
#define Dd   1024
#define Hh   16
#define DKh  64
#define Mtot (Bb * Ss)

typedef __nv_bfloat16 bf16;

__device__ bf16 g_xh[Mtot * Dd], g_xl[Mtot * Dd];
__device__ bf16 g_wth[4u * Dd * Dd], g_wtl[4u * Dd * Dd];
__device__ bf16 g_qh[Mtot * Dd], g_ql[Mtot * Dd];
__device__ bf16 g_kh[Mtot * Dd], g_kl[Mtot * Dd];
__device__ __half g_vh[Mtot * Dd], g_vl[Mtot * Dd];
__device__ bf16 g_oh[Mtot * Dd], g_ol[Mtot * Dd];

// ---------------- PTX helpers ----------------
__device__ __forceinline__ uint32_t smem_u32(const void* p) {
    uint32_t a;
    asm("{ .reg .u64 t; cvta.to.shared.u64 t, %1; cvt.u32.u64 %0, t; }" : "=r"(a) : "l"(p));
    return a;
}
__device__ __forceinline__ void cpa16(uint32_t dst, const void* src) {
    asm volatile("cp.async.ca.shared.global [%0], [%1], 16;" :: "r"(dst), "l"(src));
}
#define CP_COMMIT() asm volatile("cp.async.commit_group;" ::: "memory")
#define CP_WAIT(n)  asm volatile("cp.async.wait_group %0;" :: "n"(n) : "memory")

__device__ __forceinline__ void mma_bf16(float* c, const uint32_t* a, uint32_t b0, uint32_t b1)
{
    asm volatile(
        "mma.sync.aligned.m16n8k16.row.col.f32.bf16.bf16.f32 "
        "{%0,%1,%2,%3},{%4,%5,%6,%7},{%8,%9},{%0,%1,%2,%3};"
        : "+f"(c[0]), "+f"(c[1]), "+f"(c[2]), "+f"(c[3])
        : "r"(a[0]), "r"(a[1]), "r"(a[2]), "r"(a[3]), "r"(b0), "r"(b1));
}
__device__ __forceinline__ void mma_f16(float* c, const uint32_t* a, uint32_t b0, uint32_t b1)
{
    asm volatile(
        "mma.sync.aligned.m16n8k16.row.col.f32.f16.f16.f32 "
        "{%0,%1,%2,%3},{%4,%5,%6,%7},{%8,%9},{%0,%1,%2,%3};"
        : "+f"(c[0]), "+f"(c[1]), "+f"(c[2]), "+f"(c[3])
        : "r"(a[0]), "r"(a[1]), "r"(a[2]), "r"(a[3]), "r"(b0), "r"(b1));
}
__device__ __forceinline__ void ldmx4(uint32_t* r, uint32_t addr)
{
    asm volatile("ldmatrix.sync.aligned.m8n8.x4.shared.b16 {%0,%1,%2,%3}, [%4];"
        : "=r"(r[0]), "=r"(r[1]), "=r"(r[2]), "=r"(r[3]) : "r"(addr));
}
__device__ __forceinline__ void ldmx4t(uint32_t* r, uint32_t addr)
{
    asm volatile("ldmatrix.sync.aligned.m8n8.x4.trans.shared.b16 {%0,%1,%2,%3}, [%4];"
        : "=r"(r[0]), "=r"(r[1]), "=r"(r[2]), "=r"(r[3]) : "r"(addr));
}
__device__ __forceinline__ void packhl(float a, float b, uint32_t& hi, uint32_t& lo)
{
    __nv_bfloat162 h = __float22bfloat162_rn(make_float2(a, b));
    float2 hf = __bfloat1622float2(h);
    __nv_bfloat162 l = __float22bfloat162_rn(make_float2(a - hf.x, b - hf.y));
    hi = *(uint32_t*)&h; lo = *(uint32_t*)&l;
}
__device__ __forceinline__ uint32_t packf16(float a, float b)
{
    __half2 h = __floats2half2_rn(a, b);
    return *(uint32_t*)&h;
}

// ---------------------------------------------------------------------------
// Prep kernels
// ---------------------------------------------------------------------------
__global__ __launch_bounds__(256) void split_x(const float* __restrict__ X,
                                               bf16* __restrict__ Xh, bf16* __restrict__ Xl)
{
    int i = blockIdx.x * 256 + threadIdx.x;
    float4 v = ((const float4*)X)[i];
    uint32_t h0, l0, h1, l1;
    packhl(v.x, v.y, h0, l0);
    packhl(v.z, v.w, h1, l1);
    ((uint2*)Xh)[i] = make_uint2(h0, h1);
    ((uint2*)Xl)[i] = make_uint2(l0, l1);
}

__global__ __launch_bounds__(256) void split_wt(const float* __restrict__ W,
                                                bf16* __restrict__ Wth, bf16* __restrict__ Wtl)
{
    __shared__ float tile[32][33];
    int bx = blockIdx.x * 32, by = blockIdx.y * 32;
    int tx = threadIdx.x & 31, ty8 = threadIdx.x >> 5;
#pragma unroll
    for (int i = 0; i < 4; i++)
        tile[ty8 + i * 8][tx] = W[(size_t)(by + ty8 + i * 8) * Dd + bx + tx];
    __syncthreads();
#pragma unroll
    for (int i = 0; i < 4; i++) {
        float v = tile[tx][ty8 + i * 8];
        bf16 h = __float2bfloat16_rn(v);
        bf16 lo = __float2bfloat16_rn(v - __bfloat162float(h));
        size_t idx = (size_t)(bx + ty8 + i * 8) * Dd + by + tx;
        Wth[idx] = h; Wtl[idx] = lo;
    }
}

// ---------------------------------------------------------------------------
// 3xBF16 GEMM. OUT: 0 = fp32 C, 1 = bf16 hi/lo, 2 = fp16 hi/lo.
// CTA 128x128, 128 thr (2x2 warps, 64x64 warp tile), BK=32, cp.async 2-stage.
// All fragments via ldmatrix.x4.
// ---------------------------------------------------------------------------
#define GRS  40
#define GT_AL (128 * GRS)
#define GT_B  (2 * 128 * GRS)
#define GT_BL (3 * 128 * GRS)
#define GBUF  (4 * 128 * GRS)
#define GSM   (2 * GBUF * 2)

template<int OUT>
__global__ __launch_bounds__(128, 2) void gemm_bfhl(
    const bf16* __restrict__ Ah, const bf16* __restrict__ Al,
    const bf16* __restrict__ Bh, const bf16* __restrict__ Bl,
    const float* __restrict__ bias, float scale,
    float* __restrict__ C, void* __restrict__ ChV, void* __restrict__ ClV)
{
    extern __shared__ __align__(16) bf16 sm[];
    const int t = threadIdx.x, l = t & 31, wid = t >> 5;
    const int wm = wid >> 1, wn = wid & 1;
    const int row0 = blockIdx.y * 128, col0 = blockIdx.x * 128;
    const int lr = l >> 2, lc2 = (l & 3) * 2;
    const uint32_t sb = smem_u32(sm);

    float acc[4][8][4];
#pragma unroll
    for (int mt = 0; mt < 4; mt++)
#pragma unroll
        for (int nt = 0; nt < 8; nt++)
#pragma unroll
            for (int j = 0; j < 4; j++) acc[mt][nt][j] = 0.f;

    const int gr = t >> 2, gc8 = (t & 3) * 8;

    auto load = [&](int ch, int buf) {
        const int k0 = ch * 32;
        const uint32_t base = sb + buf * GBUF * 2;
#pragma unroll
        for (int i = 0; i < 4; i++) {
            int r = gr + i * 32;
            uint32_t doff = (r * GRS + gc8) * 2;
            cpa16(base + doff,             Ah + (size_t)(row0 + r) * Dd + k0 + gc8);
            cpa16(base + GT_AL * 2 + doff, Al + (size_t)(row0 + r) * Dd + k0 + gc8);
            cpa16(base + GT_B * 2 + doff,  Bh + (size_t)(col0 + r) * Dd + k0 + gc8);
            cpa16(base + GT_BL * 2 + doff, Bl + (size_t)(col0 + r) * Dd + k0 + gc8);
        }
    };

    // ldmatrix lane address components
    const int arow = l & 15, ako = (l >> 4) * 8;
    const int brow = (l & 7) + ((l >> 1) & 8), bko = l & 8;

    load(0, 0); CP_COMMIT();

    for (int ch = 0; ch < 32; ch++) {
        if (ch < 31) { load(ch + 1, (ch + 1) & 1); CP_COMMIT(); CP_WAIT(1); }
        else CP_WAIT(0);
        __syncthreads();

        const uint32_t bufb = sb + (ch & 1) * GBUF * 2;
        const uint32_t aHb = bufb + ((wm * 64 + arow) * GRS + ako) * 2;
        const uint32_t aLb = aHb + GT_AL * 2;
        const uint32_t bHb = bufb + GT_B * 2 + ((wn * 64 + brow) * GRS + bko) * 2;
        const uint32_t bLb = bHb + (GT_BL - GT_B) * 2;

#pragma unroll
        for (int kk = 0; kk < 2; kk++) {
            const uint32_t kb2 = kk * 32;
            uint32_t ah[4][4], al[4][4];
#pragma unroll
            for (int mt = 0; mt < 4; mt++) {
                ldmx4(ah[mt], aHb + mt * (16 * GRS * 2) + kb2);
                ldmx4(al[mt], aLb + mt * (16 * GRS * 2) + kb2);
            }
#pragma unroll
            for (int nt2 = 0; nt2 < 4; nt2++) {
                uint32_t bh[4], bl[4];
                ldmx4(bh, bHb + nt2 * (16 * GRS * 2) + kb2);
                ldmx4(bl, bLb + nt2 * (16 * GRS * 2) + kb2);
#pragma unroll
                for (int mt = 0; mt < 4; mt++) {
                    mma_bf16(acc[mt][2 * nt2],     ah[mt], bh[0], bh[1]);
                    mma_bf16(acc[mt][2 * nt2],     ah[mt], bl[0], bl[1]);
                    mma_bf16(acc[mt][2 * nt2],     al[mt], bh[0], bh[1]);
                    mma_bf16(acc[mt][2 * nt2 + 1], ah[mt], bh[2], bh[3]);
                    mma_bf16(acc[mt][2 * nt2 + 1], ah[mt], bl[2], bl[3]);
                    mma_bf16(acc[mt][2 * nt2 + 1], al[mt], bh[2], bh[3]);
                }
            }
        }
        __syncthreads();
    }

#pragma unroll
    for (int mt = 0; mt < 4; mt++) {
        const int r = row0 + wm * 64 + mt * 16 + lr;
#pragma unroll
        for (int nt = 0; nt < 8; nt++) {
            const int c = col0 + wn * 64 + nt * 8 + lc2;
            float2 bb = *(const float2*)&bias[c];
            float p0 = (acc[mt][nt][0] + bb.x) * scale;
            float p1 = (acc[mt][nt][1] + bb.y) * scale;
            float p2 = (acc[mt][nt][2] + bb.x) * scale;
            float p3 = (acc[mt][nt][3] + bb.y) * scale;
            if (OUT == 0) {
                *(float2*)(C + (size_t)r * Dd + c)       = make_float2(p0, p1);
                *(float2*)(C + (size_t)(r + 8) * Dd + c) = make_float2(p2, p3);
            } else if (OUT == 1) {
                bf16* Ch = (bf16*)ChV; bf16* Cl = (bf16*)ClV;
                uint32_t hi, lo;
                packhl(p0, p1, hi, lo);
                *(uint32_t*)&Ch[(size_t)r * Dd + c] = hi;
                *(uint32_t*)&Cl[(size_t)r * Dd + c] = lo;
                packhl(p2, p3, hi, lo);
                *(uint32_t*)&Ch[(size_t)(r + 8) * Dd + c] = hi;
                *(uint32_t*)&Cl[(size_t)(r + 8) * Dd + c] = lo;
            } else {
                __half* Ch = (__half*)ChV; __half* Cl = (__half*)ClV;
                __half2 h = __floats2half2_rn(p0, p1);
                float2 hf = __half22float2(h);
                __half2 lo = __floats2half2_rn(p0 - hf.x, p1 - hf.y);
                *(__half2*)&Ch[(size_t)r * Dd + c] = h;
                *(__half2*)&Cl[(size_t)r * Dd + c] = lo;
                h = __floats2half2_rn(p2, p3);
                hf = __half22float2(h);
                lo = __floats2half2_rn(p2 - hf.x, p3 - hf.y);
                *(__half2*)&Ch[(size_t)(r + 8) * Dd + c] = h;
                *(__half2*)&Cl[(size_t)(r + 8) * Dd + c] = lo;
            }
        }
    }
}

// ---------------------------------------------------------------------------
// Flash attention. QK: 3xBF16 (Q/K bf16 hi/lo). PV: fp16, 2 terms.
// CTA = (b,h) x 256 queries; 8 warps x 32 rows. 64 keys/chunk.
// 3-stage cp.async pipeline, ONE syncthreads per chunk.
// smem: Qh,Ql[256x72 bf16]; 3 x {Kh,Kl(bf16), Vh,Vl(fp16)}[64x72].
// ---------------------------------------------------------------------------
#define ARS 72
#define AQL (256 * ARS)
#define AKV0 (2 * 256 * ARS)
#define KVB (4 * 64 * ARS)
#define ASMB ((2 * 256 * ARS + 3 * KVB) * 2)   // 184320 bytes

__global__ __launch_bounds__(256, 1) void attn_bfhl(
    const bf16* __restrict__ Qh, const bf16* __restrict__ Ql,
    const bf16* __restrict__ Kh, const bf16* __restrict__ Kl,
    const __half* __restrict__ Vh, const __half* __restrict__ Vl,
    bf16* __restrict__ Oh, bf16* __restrict__ Ol)
{
    extern __shared__ __align__(16) bf16 sm[];
    const int t = threadIdx.x, l = t & 31, wid = t >> 5;
    const int lr = l >> 2, lc2 = (l & 3) * 2;
    const int b = blockIdx.x >> 4, h = blockIdx.x & 15, hc = h * DKh;
    const int q0 = blockIdx.y * 256, wrow = wid * 32;
    const uint32_t sb = smem_u32(sm);
    const int vkey = l & 15, vdks = (l >> 4) * 8;
    const int krow = (l & 7) + ((l >> 1) & 8), kko = l & 8;

    const size_t qoff = (size_t)(b * Ss + q0) * Dd + hc;
    const size_t kvrow0 = (size_t)(b * Ss) * Dd + hc;

    // group 0: Q tiles
    {
        const int r = t >> 3, c8 = (t & 7) * 8;
#pragma unroll
        for (int i = 0; i < 8; i++) {
            int rr = r + i * 32;
            uint32_t doff = (rr * ARS + c8) * 2;
            cpa16(sb + doff,           Qh + qoff + (size_t)rr * Dd + c8);
            cpa16(sb + AQL * 2 + doff, Ql + qoff + (size_t)rr * Dd + c8);
        }
    }
    CP_COMMIT();

    auto loadKV = [&](int ck, int buf) {
        const size_t koff = kvrow0 + (size_t)ck * 64 * Dd;
        const uint32_t base = sb + (AKV0 + buf * KVB) * 2;
        const int r = t >> 3, c8 = (t & 7) * 8;
#pragma unroll
        for (int i = 0; i < 2; i++) {
            int rr = r + i * 32;
            uint32_t doff = (rr * ARS + c8) * 2;
            const size_t goff = koff + (size_t)rr * Dd + c8;
            cpa16(base + doff,                    Kh + goff);
            cpa16(base + 1 * 64 * ARS * 2 + doff, Kl + goff);
            cpa16(base + 2 * 64 * ARS * 2 + doff, Vh + goff);
            cpa16(base + 3 * 64 * ARS * 2 + doff, Vl + goff);
        }
    };
    loadKV(0, 0); CP_COMMIT();   // group 1
    loadKV(1, 1); CP_COMMIT();   // group 2

    CP_WAIT(2);                  // Q ready
    __syncthreads();

    // persistent Q fragments
    uint32_t qhf[2][4][4], qlf[2][4][4];
#pragma unroll
    for (int mt = 0; mt < 2; mt++)
#pragma unroll
        for (int kc = 0; kc < 4; kc++)
#pragma unroll
            for (int j = 0; j < 4; j++) {
                int rr = wrow + mt * 16 + lr + (j & 1) * 8;
                int cc = kc * 16 + (j >> 1) * 8 + lc2;
                qhf[mt][kc][j] = *(const uint32_t*)&sm[rr * ARS + cc];
                qlf[mt][kc][j] = *(const uint32_t*)&sm[AQL + rr * ARS + cc];
            }

    float mrow[2][2], lrow[2][2];
    float o[2][8][4];
#pragma unroll
    for (int mt = 0; mt < 2; mt++) {
        mrow[mt][0] = mrow[mt][1] = -INFINITY;
        lrow[mt][0] = lrow[mt][1] = 0.f;
#pragma unroll
        for (int nt = 0; nt < 8; nt++)
#pragma unroll
            for (int j = 0; j < 4; j++) o[mt][nt][j] = 0.f;
    }

    for (int ck = 0; ck < 32; ck++) {
        CP_WAIT(1);              // buffer ck%3 complete (per-thread)
        __syncthreads();         // visible to all; prior compute done
        if (ck + 2 < 32) { loadKV(ck + 2, (ck + 2) % 3); CP_COMMIT(); }

        const int buf = ck % 3;
        const uint32_t kvb = sb + (AKV0 + buf * KVB) * 2;
        const uint32_t kHb = kvb + ((krow)*ARS + kko) * 2;
        const uint32_t kLb = kHb + 64 * ARS * 2;
        const uint32_t vh32 = kvb + 2 * 64 * ARS * 2;
        const uint32_t vl32 = vh32 + 64 * ARS * 2;

        // S = Q K^T (3xBF16), K frags via ldmatrix
        float s[2][8][4];
#pragma unroll
        for (int mt = 0; mt < 2; mt++)
#pragma unroll
            for (int nt = 0; nt < 8; nt++)
                s[mt][nt][0] = s[mt][nt][1] = s[mt][nt][2] = s[mt][nt][3] = 0.f;
#pragma unroll
        for (int nt2 = 0; nt2 < 4; nt2++) {
#pragma unroll
            for (int kc = 0; kc < 4; kc++) {
                const uint32_t off = nt2 * (16 * ARS * 2) + kc * 32;
                uint32_t kh4[4], kl4[4];
                ldmx4(kh4, kHb + off);
                ldmx4(kl4, kLb + off);
#pragma unroll
                for (int mt = 0; mt < 2; mt++) {
                    mma_bf16(s[mt][2 * nt2],     qhf[mt][kc], kh4[0], kh4[1]);
                    mma_bf16(s[mt][2 * nt2],     qhf[mt][kc], kl4[0], kl4[1]);
                    mma_bf16(s[mt][2 * nt2],     qlf[mt][kc], kh4[0], kh4[1]);
                    mma_bf16(s[mt][2 * nt2 + 1], qhf[mt][kc], kh4[2], kh4[3]);
                    mma_bf16(s[mt][2 * nt2 + 1], qhf[mt][kc], kl4[2], kl4[3]);
                    mma_bf16(s[mt][2 * nt2 + 1], qlf[mt][kc], kh4[2], kh4[3]);
                }
            }
        }

        // online softmax
#pragma unroll
        for (int mt = 0; mt < 2; mt++) {
            float mx0 = s[mt][0][0], mx1 = s[mt][0][2];
#pragma unroll
            for (int nt = 0; nt < 8; nt++) {
                mx0 = fmaxf(mx0, fmaxf(s[mt][nt][0], s[mt][nt][1]));
                mx1 = fmaxf(mx1, fmaxf(s[mt][nt][2], s[mt][nt][3]));
            }
            mx0 = fmaxf(mx0, __shfl_xor_sync(0xffffffffu, mx0, 1));
            mx0 = fmaxf(mx0, __shfl_xor_sync(0xffffffffu, mx0, 2));
            mx1 = fmaxf(mx1, __shfl_xor_sync(0xffffffffu, mx1, 1));
            mx1 = fmaxf(mx1, __shfl_xor_sync(0xffffffffu, mx1, 2));
            float mn0 = fmaxf(mrow[mt][0], mx0), mn1 = fmaxf(mrow[mt][1], mx1);
            float c0 = __expf(mrow[mt][0] - mn0), c1 = __expf(mrow[mt][1] - mn1);
            mrow[mt][0] = mn0; mrow[mt][1] = mn1;
            float sum0 = 0.f, sum1 = 0.f;
#pragma unroll
            for (int nt = 0; nt < 8; nt++) {
                s[mt][nt][0] = __expf(s[mt][nt][0] - mn0);
                s[mt][nt][1] = __expf(s[mt][nt][1] - mn0);
                s[mt][nt][2] = __expf(s[mt][nt][2] - mn1);
                s[mt][nt][3] = __expf(s[mt][nt][3] - mn1);
                sum0 += s[mt][nt][0] + s[mt][nt][1];
                sum1 += s[mt][nt][2] + s[mt][nt][3];
            }
            sum0 += __shfl_xor_sync(0xffffffffu, sum0, 1);
            sum0 += __shfl_xor_sync(0xffffffffu, sum0, 2);
            sum1 += __shfl_xor_sync(0xffffffffu, sum1, 1);
            sum1 += __shfl_xor_sync(0xffffffffu, sum1, 2);
            lrow[mt][0] = lrow[mt][0] * c0 + sum0;
            lrow[mt][1] = lrow[mt][1] * c1 + sum1;
#pragma unroll
            for (int nt = 0; nt < 8; nt++) {
                o[mt][nt][0] *= c0; o[mt][nt][1] *= c0;
                o[mt][nt][2] *= c1; o[mt][nt][3] *= c1;
            }
        }

        // O += P @ V : P fp16 single, V = Vh+Vl fp16
#pragma unroll
        for (int kc = 0; kc < 4; kc++) {
            uint32_t pf[2][4];
#pragma unroll
            for (int mt = 0; mt < 2; mt++) {
                pf[mt][0] = packf16(s[mt][2 * kc][0],     s[mt][2 * kc][1]);
                pf[mt][1] = packf16(s[mt][2 * kc][2],     s[mt][2 * kc][3]);
                pf[mt][2] = packf16(s[mt][2 * kc + 1][0], s[mt][2 * kc + 1][1]);
                pf[mt][3] = packf16(s[mt][2 * kc + 1][2], s[mt][2 * kc + 1][3]);
            }
            const uint32_t rowoff = ((kc * 16 + vkey) * ARS + vdks) * 2;
#pragma unroll
            for (int np = 0; np < 4; np++) {
                uint32_t rh[4], rl[4];
                ldmx4t(rh, vh32 + rowoff + np * 32);
                ldmx4t(rl, vl32 + rowoff + np * 32);
#pragma unroll
                for (int mt = 0; mt < 2; mt++) {
                    mma_f16(o[mt][2 * np],     pf[mt], rh[0], rh[1]);
                    mma_f16(o[mt][2 * np],     pf[mt], rl[0], rl[1]);
                    mma_f16(o[mt][2 * np + 1], pf[mt], rh[2], rh[3]);
                    mma_f16(o[mt][2 * np + 1], pf[mt], rl[2], rl[3]);
                }
            }
        }
    }

    // finalize: normalize, split bf16 hi/lo, store
#pragma unroll
    for (int mt = 0; mt < 2; mt++) {
        float i0 = 1.f / lrow[mt][0], i1 = 1.f / lrow[mt][1];
        const size_t r0 = (size_t)(b * Ss + q0 + wrow + mt * 16 + lr) * Dd + hc;
#pragma unroll
        for (int nt = 0; nt < 8; nt++) {
            uint32_t hi, lo;
            packhl(o[mt][nt][0] * i0, o[mt][nt][1] * i0, hi, lo);
            *(uint32_t*)&Oh[r0 + nt * 8 + lc2] = hi;
            *(uint32_t*)&Ol[r0 + nt * 8 + lc2] = lo;
            packhl(o[mt][nt][2] * i1, o[mt][nt][3] * i1, hi, lo);
            *(uint32_t*)&Oh[r0 + 8 * Dd + nt * 8 + lc2] = hi;
            *(uint32_t*)&Ol[r0 + 8 * Dd + nt * 8 + lc2] = lo;
        }
    }
}

// ---------------------------------------------------------------------------
extern "C" void kernel_launch(void* const* d_in, const int* in_sizes, int n_in,
                              void* d_out, int out_size)
{
    const float* x  = (const float*)d_in[0];
    const float* Wq = (const float*)d_in[1];
    const float* bq = (const float*)d_in[2];
    const float* Wk = (const float*)d_in[3];
    const float* bk = (const float*)d_in[4];
    const float* Wv = (const float*)d_in[5];
    const float* bv = (const float*)d_in[6];
    const float* Wo = (const float*)d_in[7];
    const float* bo = (const float*)d_in[8];
    float* out = (float*)d_out;

    bf16 *xh, *xl, *wth, *wtl, *qh, *ql, *kh, *kl, *oh, *ol;
    __half *vh, *vl;
    cudaGetSymbolAddress((void**)&xh, g_xh);  cudaGetSymbolAddress((void**)&xl, g_xl);
    cudaGetSymbolAddress((void**)&wth, g_wth); cudaGetSymbolAddress((void**)&wtl, g_wtl);
    cudaGetSymbolAddress((void**)&qh, g_qh);  cudaGetSymbolAddress((void**)&ql, g_ql);
    cudaGetSymbolAddress((void**)&kh, g_kh);  cudaGetSymbolAddress((void**)&kl, g_kl);
    cudaGetSymbolAddress((void**)&vh, g_vh);  cudaGetSymbolAddress((void**)&vl, g_vl);
    cudaGetSymbolAddress((void**)&oh, g_oh);  cudaGetSymbolAddress((void**)&ol, g_ol);

    cudaFuncSetAttribute(gemm_bfhl<0>, cudaFuncAttributeMaxDynamicSharedMemorySize, GSM);
    cudaFuncSetAttribute(gemm_bfhl<1>, cudaFuncAttributeMaxDynamicSharedMemorySize, GSM);
    cudaFuncSetAttribute(gemm_bfhl<2>, cudaFuncAttributeMaxDynamicSharedMemorySize, GSM);
    cudaFuncSetAttribute(attn_bfhl,    cudaFuncAttributeMaxDynamicSharedMemorySize, ASMB);

    split_x<<<Mtot * Dd / 4 / 256, 256>>>(x, xh, xl);
    dim3 tGrid(32, 32);
    split_wt<<<tGrid, 256>>>(Wq, wth + 0u * Dd * Dd, wtl + 0u * Dd * Dd);
    split_wt<<<tGrid, 256>>>(Wk, wth + 1u * Dd * Dd, wtl + 1u * Dd * Dd);
    split_wt<<<tGrid, 256>>>(Wv, wth + 2u * Dd * Dd, wtl + 2u * Dd * Dd);
    split_wt<<<tGrid, 256>>>(Wo, wth + 3u * Dd * Dd, wtl + 3u * Dd * Dd);

    dim3 gGrid(Dd / 128, Mtot / 128);
    gemm_bfhl<1><<<gGrid, 128, GSM>>>(xh, xl, wth + 0u * Dd * Dd, wtl + 0u * Dd * Dd,
                                      bq, 0.125f, nullptr, qh, ql);
    gemm_bfhl<1><<<gGrid, 128, GSM>>>(xh, xl, wth + 1u * Dd * Dd, wtl + 1u * Dd * Dd,
                                      bk, 1.0f, nullptr, kh, kl);
    gemm_bfhl<2><<<gGrid, 128, GSM>>>(xh, xl, wth + 2u * Dd * Dd, wtl + 2u * Dd * Dd,
                                      bv, 1.0f, nullptr, vh, vl);

    attn_bfhl<<<dim3(Bb * Hh, Ss / 256), 256, ASMB>>>(qh, ql, kh, kl, vh, vl, oh, ol);

    gemm_bfhl<0><<<gGrid, 128, GSM>>>(oh, ol, wth + 3u * Dd * Dd, wtl + 3u * Dd * Dd,
                                      bo, 1.0f, out, nullptr, nullptr);
}

// round 9
// speedup vs baseline: 6.2916x; 1.0788x over previous
#include <cuda_runtime.h>
#include <cuda_bf16.h>
#include <cuda_fp16.h>
#include <cstdint>

#define Bb   2
#define Ss   2048
#define Dd   1024
#define Hh   16
#define DKh  64
#define Mtot (Bb * Ss)

typedef __nv_bfloat16 bf16;

__device__ bf16 g_xh[Mtot * Dd], g_xl[Mtot * Dd];
__device__ bf16 g_wth[4u * Dd * Dd], g_wtl[4u * Dd * Dd];
__device__ __half g_qh[Mtot * Dd], g_ql[Mtot * Dd];
__device__ __half g_kh[Mtot * Dd];
__device__ __half g_vh[Mtot * Dd], g_vl[Mtot * Dd];
__device__ bf16 g_oh[Mtot * Dd], g_ol[Mtot * Dd];

// ---------------- PTX helpers ----------------
__device__ __forceinline__ uint32_t smem_u32(const void* p) {
    uint32_t a;
    asm("{ .reg .u64 t; cvta.to.shared.u64 t, %1; cvt.u32.u64 %0, t; }" : "=r"(a) : "l"(p));
    return a;
}
__device__ __forceinline__ void cpa16(uint32_t dst, const void* src) {
    asm volatile("cp.async.ca.shared.global [%0], [%1], 16;" :: "r"(dst), "l"(src));
}
#define CP_COMMIT() asm volatile("cp.async.commit_group;" ::: "memory")
#define CP_WAIT(n)  asm volatile("cp.async.wait_group %0;" :: "n"(n) : "memory")

__device__ __forceinline__ void mma_bf16(float* c, const uint32_t* a, uint32_t b0, uint32_t b1)
{
    asm volatile(
        "mma.sync.aligned.m16n8k16.row.col.f32.bf16.bf16.f32 "
        "{%0,%1,%2,%3},{%4,%5,%6,%7},{%8,%9},{%0,%1,%2,%3};"
        : "+f"(c[0]), "+f"(c[1]), "+f"(c[2]), "+f"(c[3])
        : "r"(a[0]), "r"(a[1]), "r"(a[2]), "r"(a[3]), "r"(b0), "r"(b1));
}
__device__ __forceinline__ void mma_f16(float* c, const uint32_t* a, uint32_t b0, uint32_t b1)
{
    asm volatile(
        "mma.sync.aligned.m16n8k16.row.col.f32.f16.f16.f32 "
        "{%0,%1,%2,%3},{%4,%5,%6,%7},{%8,%9},{%0,%1,%2,%3};"
        : "+f"(c[0]), "+f"(c[1]), "+f"(c[2]), "+f"(c[3])
        : "r"(a[0]), "r"(a[1]), "r"(a[2]), "r"(a[3]), "r"(b0), "r"(b1));
}
__device__ __forceinline__ void ldmx4(uint32_t* r, uint32_t addr)
{
    asm volatile("ldmatrix.sync.aligned.m8n8.x4.shared.b16 {%0,%1,%2,%3}, [%4];"
        : "=r"(r[0]), "=r"(r[1]), "=r"(r[2]), "=r"(r[3]) : "r"(addr));
}
__device__ __forceinline__ void ldmx4t(uint32_t* r, uint32_t addr)
{
    asm volatile("ldmatrix.sync.aligned.m8n8.x4.trans.shared.b16 {%0,%1,%2,%3}, [%4];"
        : "=r"(r[0]), "=r"(r[1]), "=r"(r[2]), "=r"(r[3]) : "r"(addr));
}
__device__ __forceinline__ void packhl(float a, float b, uint32_t& hi, uint32_t& lo)
{
    __nv_bfloat162 h = __float22bfloat162_rn(make_float2(a, b));
    float2 hf = __bfloat1622float2(h);
    __nv_bfloat162 l = __float22bfloat162_rn(make_float2(a - hf.x, b - hf.y));
    hi = *(uint32_t*)&h; lo = *(uint32_t*)&l;
}
__device__ __forceinline__ uint32_t packf16(float a, float b)
{
    __half2 h = __floats2half2_rn(a, b);
    return *(uint32_t*)&h;
}

// ---------------------------------------------------------------------------
// Prep kernels
// ---------------------------------------------------------------------------
__global__ __launch_bounds__(256) void split_x(const float* __restrict__ X,
                                               bf16* __restrict__ Xh, bf16* __restrict__ Xl)
{
    int i = blockIdx.x * 256 + threadIdx.x;
    float4 v = ((const float4*)X)[i];
    uint32_t h0, l0, h1, l1;
    packhl(v.x, v.y, h0, l0);
    packhl(v.z, v.w, h1, l1);
    ((uint2*)Xh)[i] = make_uint2(h0, h1);
    ((uint2*)Xl)[i] = make_uint2(l0, l1);
}

__global__ __launch_bounds__(256) void split_wt4(
    const float* __restrict__ W0, const float* __restrict__ W1,
    const float* __restrict__ W2, const float* __restrict__ W3,
    bf16* __restrict__ Wth, bf16* __restrict__ Wtl)
{
    __shared__ float tile[32][33];
    const float* W = (blockIdx.z == 0) ? W0 : (blockIdx.z == 1) ? W1 : (blockIdx.z == 2) ? W2 : W3;
    bf16* oh = Wth + (size_t)blockIdx.z * Dd * Dd;
    bf16* ol = Wtl + (size_t)blockIdx.z * Dd * Dd;
    int bx = blockIdx.x * 32, by = blockIdx.y * 32;
    int tx = threadIdx.x & 31, ty8 = threadIdx.x >> 5;
#pragma unroll
    for (int i = 0; i < 4; i++)
        tile[ty8 + i * 8][tx] = W[(size_t)(by + ty8 + i * 8) * Dd + bx + tx];
    __syncthreads();
#pragma unroll
    for (int i = 0; i < 4; i++) {
        float v = tile[tx][ty8 + i * 8];
        bf16 h = __float2bfloat16_rn(v);
        bf16 lo = __float2bfloat16_rn(v - __bfloat162float(h));
        size_t idx = (size_t)(bx + ty8 + i * 8) * Dd + by + tx;
        oh[idx] = h; ol[idx] = lo;
    }
}

// ---------------------------------------------------------------------------
// 3xBF16 GEMM. OUT: 0 fp32, 1 bf16 hi/lo, 2 fp16 hi/lo, 3 fp16 single.
// ---------------------------------------------------------------------------
#define GRS  40
#define GT_AL (128 * GRS)
#define GT_B  (2 * 128 * GRS)
#define GT_BL (3 * 128 * GRS)
#define GBUF  (4 * 128 * GRS)
#define GSM   (2 * GBUF * 2)

extern __shared__ __align__(16) char dynsm[];

template<int OUT>
__global__ __launch_bounds__(128, 2) void gemm_bfhl(
    const bf16* __restrict__ Ah, const bf16* __restrict__ Al,
    const bf16* __restrict__ Bh, const bf16* __restrict__ Bl,
    const float* __restrict__ bias, float scale,
    float* __restrict__ C, void* __restrict__ ChV, void* __restrict__ ClV)
{
    bf16* sm = (bf16*)dynsm;
    const int t = threadIdx.x, l = t & 31, wid = t >> 5;
    const int wm = wid >> 1, wn = wid & 1;
    const int row0 = blockIdx.y * 128, col0 = blockIdx.x * 128;
    const int lr = l >> 2, lc2 = (l & 3) * 2;
    const uint32_t sb = smem_u32(sm);

    float acc[4][8][4];
#pragma unroll
    for (int mt = 0; mt < 4; mt++)
#pragma unroll
        for (int nt = 0; nt < 8; nt++)
#pragma unroll
            for (int j = 0; j < 4; j++) acc[mt][nt][j] = 0.f;

    const int gr = t >> 2, gc8 = (t & 3) * 8;

    auto load = [&](int ch, int buf) {
        const int k0 = ch * 32;
        const uint32_t base = sb + buf * GBUF * 2;
#pragma unroll
        for (int i = 0; i < 4; i++) {
            int r = gr + i * 32;
            uint32_t doff = (r * GRS + gc8) * 2;
            cpa16(base + doff,             Ah + (size_t)(row0 + r) * Dd + k0 + gc8);
            cpa16(base + GT_AL * 2 + doff, Al + (size_t)(row0 + r) * Dd + k0 + gc8);
            cpa16(base + GT_B * 2 + doff,  Bh + (size_t)(col0 + r) * Dd + k0 + gc8);
            cpa16(base + GT_BL * 2 + doff, Bl + (size_t)(col0 + r) * Dd + k0 + gc8);
        }
    };

    const int arow = l & 15, ako = (l >> 4) * 8;
    const int brow = (l & 7) + ((l >> 1) & 8), bko = l & 8;

    load(0, 0); CP_COMMIT();

    for (int ch = 0; ch < 32; ch++) {
        if (ch < 31) { load(ch + 1, (ch + 1) & 1); CP_COMMIT(); CP_WAIT(1); }
        else CP_WAIT(0);
        __syncthreads();

        const uint32_t bufb = sb + (ch & 1) * GBUF * 2;
        const uint32_t aHb = bufb + ((wm * 64 + arow) * GRS + ako) * 2;
        const uint32_t aLb = aHb + GT_AL * 2;
        const uint32_t bHb = bufb + GT_B * 2 + ((wn * 64 + brow) * GRS + bko) * 2;
        const uint32_t bLb = bHb + (GT_BL - GT_B) * 2;

#pragma unroll
        for (int kk = 0; kk < 2; kk++) {
            const uint32_t kb2 = kk * 32;
            uint32_t ah[4][4], al[4][4];
#pragma unroll
            for (int mt = 0; mt < 4; mt++) {
                ldmx4(ah[mt], aHb + mt * (16 * GRS * 2) + kb2);
                ldmx4(al[mt], aLb + mt * (16 * GRS * 2) + kb2);
            }
#pragma unroll
            for (int nt2 = 0; nt2 < 4; nt2++) {
                uint32_t bh[4], bl[4];
                ldmx4(bh, bHb + nt2 * (16 * GRS * 2) + kb2);
                ldmx4(bl, bLb + nt2 * (16 * GRS * 2) + kb2);
#pragma unroll
                for (int mt = 0; mt < 4; mt++) {
                    mma_bf16(acc[mt][2 * nt2],     ah[mt], bh[0], bh[1]);
                    mma_bf16(acc[mt][2 * nt2],     ah[mt], bl[0], bl[1]);
                    mma_bf16(acc[mt][2 * nt2],     al[mt], bh[0], bh[1]);
                    mma_bf16(acc[mt][2 * nt2 + 1], ah[mt], bh[2], bh[3]);
                    mma_bf16(acc[mt][2 * nt2 + 1], ah[mt], bl[2], bl[3]);
                    mma_bf16(acc[mt][2 * nt2 + 1], al[mt], bh[2], bh[3]);
                }
            }
        }
        __syncthreads();
    }

#pragma unroll
    for (int mt = 0; mt < 4; mt++) {
        const int r = row0 + wm * 64 + mt * 16 + lr;
#pragma unroll
        for (int nt = 0; nt < 8; nt++) {
            const int c = col0 + wn * 64 + nt * 8 + lc2;
            float2 bb = *(const float2*)&bias[c];
            float p0 = (acc[mt][nt][0] + bb.x) * scale;
            float p1 = (acc[mt][nt][1] + bb.y) * scale;
            float p2 = (acc[mt][nt][2] + bb.x) * scale;
            float p3 = (acc[mt][nt][3] + bb.y) * scale;
            if (OUT == 0) {
                *(float2*)(C + (size_t)r * Dd + c)       = make_float2(p0, p1);
                *(float2*)(C + (size_t)(r + 8) * Dd + c) = make_float2(p2, p3);
            } else if (OUT == 1) {
                bf16* Ch = (bf16*)ChV; bf16* Cl = (bf16*)ClV;
                uint32_t hi, lo;
                packhl(p0, p1, hi, lo);
                *(uint32_t*)&Ch[(size_t)r * Dd + c] = hi;
                *(uint32_t*)&Cl[(size_t)r * Dd + c] = lo;
                packhl(p2, p3, hi, lo);
                *(uint32_t*)&Ch[(size_t)(r + 8) * Dd + c] = hi;
                *(uint32_t*)&Cl[(size_t)(r + 8) * Dd + c] = lo;
            } else if (OUT == 2) {
                __half* Ch = (__half*)ChV; __half* Cl = (__half*)ClV;
                __half2 h = __floats2half2_rn(p0, p1);
                float2 hf = __half22float2(h);
                __half2 lo = __floats2half2_rn(p0 - hf.x, p1 - hf.y);
                *(__half2*)&Ch[(size_t)r * Dd + c] = h;
                *(__half2*)&Cl[(size_t)r * Dd + c] = lo;
                h = __floats2half2_rn(p2, p3);
                hf = __half22float2(h);
                lo = __floats2half2_rn(p2 - hf.x, p3 - hf.y);
                *(__half2*)&Ch[(size_t)(r + 8) * Dd + c] = h;
                *(__half2*)&Cl[(size_t)(r + 8) * Dd + c] = lo;
            } else {
                __half* Ch = (__half*)ChV;
                *(__half2*)&Ch[(size_t)r * Dd + c]       = __floats2half2_rn(p0, p1);
                *(__half2*)&Ch[(size_t)(r + 8) * Dd + c] = __floats2half2_rn(p2, p3);
            }
        }
    }
}

// ---------------------------------------------------------------------------
// Flash attention. QK: fp16 2-term (Q hi/lo regs, K single). PV: fp16 2-term.
// CTA = (b,h) x 256 queries; 8 warps x 32 rows. 64 keys/chunk, 3-stage pipe.
// smem: Qh,Ql[256x72 fp16]; 3 x {K, Vh, Vl}[64x72 fp16].
// ---------------------------------------------------------------------------
#define ARS 72
#define AQL (256 * ARS)
#define AKV0 (2 * 256 * ARS)
#define KVB (3 * 64 * ARS)
#define ASMB ((AKV0 + 3 * KVB) * 2)   // 156672 bytes

__global__ __launch_bounds__(256, 1) void attn_f16(
    const __half* __restrict__ Qh, const __half* __restrict__ Ql,
    const __half* __restrict__ Kh,
    const __half* __restrict__ Vh, const __half* __restrict__ Vl,
    bf16* __restrict__ Oh, bf16* __restrict__ Ol)
{
    __half* sm = (__half*)dynsm;
    const int t = threadIdx.x, l = t & 31, wid = t >> 5;
    const int lr = l >> 2, lc2 = (l & 3) * 2;
    const int b = blockIdx.x >> 4, h = blockIdx.x & 15, hc = h * DKh;
    const int q0 = blockIdx.y * 256, wrow = wid * 32;
    const uint32_t sb = smem_u32(sm);
    const int vkey = l & 15, vdks = (l >> 4) * 8;
    const int krow = (l & 7) + ((l >> 1) & 8), kko = l & 8;

    const size_t qoff = (size_t)(b * Ss + q0) * Dd + hc;
    const size_t kvrow0 = (size_t)(b * Ss) * Dd + hc;

    // group 0: Q tiles
    {
        const int r = t >> 3, c8 = (t & 7) * 8;
#pragma unroll
        for (int i = 0; i < 8; i++) {
            int rr = r + i * 32;
            uint32_t doff = (rr * ARS + c8) * 2;
            cpa16(sb + doff,           Qh + qoff + (size_t)rr * Dd + c8);
            cpa16(sb + AQL * 2 + doff, Ql + qoff + (size_t)rr * Dd + c8);
        }
    }
    CP_COMMIT();

    auto loadKV = [&](int ck, int buf) {
        const size_t koff = kvrow0 + (size_t)ck * 64 * Dd;
        const uint32_t base = sb + (AKV0 + buf * KVB) * 2;
        const int r = t >> 3, c8 = (t & 7) * 8;
#pragma unroll
        for (int i = 0; i < 2; i++) {
            int rr = r + i * 32;
            uint32_t doff = (rr * ARS + c8) * 2;
            const size_t goff = koff + (size_t)rr * Dd + c8;
            cpa16(base + doff,                    Kh + goff);
            cpa16(base + 1 * 64 * ARS * 2 + doff, Vh + goff);
            cpa16(base + 2 * 64 * ARS * 2 + doff, Vl + goff);
        }
    };
    loadKV(0, 0); CP_COMMIT();
    loadKV(1, 1); CP_COMMIT();

    CP_WAIT(2);
    __syncthreads();

    // persistent Q fragments (fp16 hi/lo)
    uint32_t qhf[2][4][4], qlf[2][4][4];
#pragma unroll
    for (int mt = 0; mt < 2; mt++)
#pragma unroll
        for (int kc = 0; kc < 4; kc++)
#pragma unroll
            for (int j = 0; j < 4; j++) {
                int rr = wrow + mt * 16 + lr + (j & 1) * 8;
                int cc = kc * 16 + (j >> 1) * 8 + lc2;
                qhf[mt][kc][j] = *(const uint32_t*)&sm[rr * ARS + cc];
                qlf[mt][kc][j] = *(const uint32_t*)&sm[AQL + rr * ARS + cc];
            }

    float mrow[2][2], lrow[2][2];
    float o[2][8][4];
#pragma unroll
    for (int mt = 0; mt < 2; mt++) {
        mrow[mt][0] = mrow[mt][1] = -INFINITY;
        lrow[mt][0] = lrow[mt][1] = 0.f;
#pragma unroll
        for (int nt = 0; nt < 8; nt++)
#pragma unroll
            for (int j = 0; j < 4; j++) o[mt][nt][j] = 0.f;
    }

    for (int ck = 0; ck < 32; ck++) {
        CP_WAIT(1);
        __syncthreads();
        if (ck + 2 < 32) { loadKV(ck + 2, (ck + 2) % 3); CP_COMMIT(); }

        const int buf = ck % 3;
        const uint32_t kvb = sb + (AKV0 + buf * KVB) * 2;
        const uint32_t kHb = kvb + (krow * ARS + kko) * 2;
        const uint32_t vh32 = kvb + 64 * ARS * 2;
        const uint32_t vl32 = vh32 + 64 * ARS * 2;

        // S = Q K^T : 2 MMAs (Qh,Ql) x K-single
        float s[2][8][4];
#pragma unroll
        for (int mt = 0; mt < 2; mt++)
#pragma unroll
            for (int nt = 0; nt < 8; nt++)
                s[mt][nt][0] = s[mt][nt][1] = s[mt][nt][2] = s[mt][nt][3] = 0.f;
#pragma unroll
        for (int nt2 = 0; nt2 < 4; nt2++) {
#pragma unroll
            for (int kc = 0; kc < 4; kc++) {
                uint32_t kh4[4];
                ldmx4(kh4, kHb + nt2 * (16 * ARS * 2) + kc * 32);
#pragma unroll
                for (int mt = 0; mt < 2; mt++) {
                    mma_f16(s[mt][2 * nt2],     qhf[mt][kc], kh4[0], kh4[1]);
                    mma_f16(s[mt][2 * nt2],     qlf[mt][kc], kh4[0], kh4[1]);
                    mma_f16(s[mt][2 * nt2 + 1], qhf[mt][kc], kh4[2], kh4[3]);
                    mma_f16(s[mt][2 * nt2 + 1], qlf[mt][kc], kh4[2], kh4[3]);
                }
            }
        }

        // online softmax
#pragma unroll
        for (int mt = 0; mt < 2; mt++) {
            float mx0 = s[mt][0][0], mx1 = s[mt][0][2];
#pragma unroll
            for (int nt = 0; nt < 8; nt++) {
                mx0 = fmaxf(mx0, fmaxf(s[mt][nt][0], s[mt][nt][1]));
                mx1 = fmaxf(mx1, fmaxf(s[mt][nt][2], s[mt][nt][3]));
            }
            mx0 = fmaxf(mx0, __shfl_xor_sync(0xffffffffu, mx0, 1));
            mx0 = fmaxf(mx0, __shfl_xor_sync(0xffffffffu, mx0, 2));
            mx1 = fmaxf(mx1, __shfl_xor_sync(0xffffffffu, mx1, 1));
            mx1 = fmaxf(mx1, __shfl_xor_sync(0xffffffffu, mx1, 2));
            float mn0 = fmaxf(mrow[mt][0], mx0), mn1 = fmaxf(mrow[mt][1], mx1);
            float c0 = __expf(mrow[mt][0] - mn0), c1 = __expf(mrow[mt][1] - mn1);
            mrow[mt][0] = mn0; mrow[mt][1] = mn1;
            float sum0 = 0.f, sum1 = 0.f;
#pragma unroll
            for (int nt = 0; nt < 8; nt++) {
                s[mt][nt][0] = __expf(s[mt][nt][0] - mn0);
                s[mt][nt][1] = __expf(s[mt][nt][1] - mn0);
                s[mt][nt][2] = __expf(s[mt][nt][2] - mn1);
                s[mt][nt][3] = __expf(s[mt][nt][3] - mn1);
                sum0 += s[mt][nt][0] + s[mt][nt][1];
                sum1 += s[mt][nt][2] + s[mt][nt][3];
            }
            sum0 += __shfl_xor_sync(0xffffffffu, sum0, 1);
            sum0 += __shfl_xor_sync(0xffffffffu, sum0, 2);
            sum1 += __shfl_xor_sync(0xffffffffu, sum1, 1);
            sum1 += __shfl_xor_sync(0xffffffffu, sum1, 2);
            lrow[mt][0] = lrow[mt][0] * c0 + sum0;
            lrow[mt][1] = lrow[mt][1] * c1 + sum1;
#pragma unroll
            for (int nt = 0; nt < 8; nt++) {
                o[mt][nt][0] *= c0; o[mt][nt][1] *= c0;
                o[mt][nt][2] *= c1; o[mt][nt][3] *= c1;
            }
        }

        // O += P @ V (P single fp16, V hi/lo)
#pragma unroll
        for (int kc = 0; kc < 4; kc++) {
            uint32_t pf[2][4];
#pragma unroll
            for (int mt = 0; mt < 2; mt++) {
                pf[mt][0] = packf16(s[mt][2 * kc][0],     s[mt][2 * kc][1]);
                pf[mt][1] = packf16(s[mt][2 * kc][2],     s[mt][2 * kc][3]);
                pf[mt][2] = packf16(s[mt][2 * kc + 1][0], s[mt][2 * kc + 1][1]);
                pf[mt][3] = packf16(s[mt][2 * kc + 1][2], s[mt][2 * kc + 1][3]);
            }
            const uint32_t rowoff = ((kc * 16 + vkey) * ARS + vdks) * 2;
#pragma unroll
            for (int np = 0; np < 4; np++) {
                uint32_t rh[4], rl[4];
                ldmx4t(rh, vh32 + rowoff + np * 32);
                ldmx4t(rl, vl32 + rowoff + np * 32);
#pragma unroll
                for (int mt = 0; mt < 2; mt++) {
                    mma_f16(o[mt][2 * np],     pf[mt], rh[0], rh[1]);
                    mma_f16(o[mt][2 * np],     pf[mt], rl[0], rl[1]);
                    mma_f16(o[mt][2 * np + 1], pf[mt], rh[2], rh[3]);
                    mma_f16(o[mt][2 * np + 1], pf[mt], rl[2], rl[3]);
                }
            }
        }
    }

    // finalize
#pragma unroll
    for (int mt = 0; mt < 2; mt++) {
        float i0 = 1.f / lrow[mt][0], i1 = 1.f / lrow[mt][1];
        const size_t r0 = (size_t)(b * Ss + q0 + wrow + mt * 16 + lr) * Dd + hc;
#pragma unroll
        for (int nt = 0; nt < 8; nt++) {
            uint32_t hi, lo;
            packhl(o[mt][nt][0] * i0, o[mt][nt][1] * i0, hi, lo);
            *(uint32_t*)&Oh[r0 + nt * 8 + lc2] = hi;
            *(uint32_t*)&Ol[r0 + nt * 8 + lc2] = lo;
            packhl(o[mt][nt][2] * i1, o[mt][nt][3] * i1, hi, lo);
            *(uint32_t*)&Oh[r0 + 8 * Dd + nt * 8 + lc2] = hi;
            *(uint32_t*)&Ol[r0 + 8 * Dd + nt * 8 + lc2] = lo;
        }
    }
}

// ---------------------------------------------------------------------------
extern "C" void kernel_launch(void* const* d_in, const int* in_sizes, int n_in,
                              void* d_out, int out_size)
{
    const float* x  = (const float*)d_in[0];
    const float* Wq = (const float*)d_in[1];
    const float* bq = (const float*)d_in[2];
    const float* Wk = (const float*)d_in[3];
    const float* bk = (const float*)d_in[4];
    const float* Wv = (const float*)d_in[5];
    const float* bv = (const float*)d_in[6];
    const float* Wo = (const float*)d_in[7];
    const float* bo = (const float*)d_in[8];
    float* out = (float*)d_out;

    bf16 *xh, *xl, *wth, *wtl, *oh, *ol;
    __half *qh, *ql, *kh, *vh, *vl;
    cudaGetSymbolAddress((void**)&xh, g_xh);  cudaGetSymbolAddress((void**)&xl, g_xl);
    cudaGetSymbolAddress((void**)&wth, g_wth); cudaGetSymbolAddress((void**)&wtl, g_wtl);
    cudaGetSymbolAddress((void**)&qh, g_qh);  cudaGetSymbolAddress((void**)&ql, g_ql);
    cudaGetSymbolAddress((void**)&kh, g_kh);
    cudaGetSymbolAddress((void**)&vh, g_vh);  cudaGetSymbolAddress((void**)&vl, g_vl);
    cudaGetSymbolAddress((void**)&oh, g_oh);  cudaGetSymbolAddress((void**)&ol, g_ol);

    cudaFuncSetAttribute(gemm_bfhl<0>, cudaFuncAttributeMaxDynamicSharedMemorySize, GSM);
    cudaFuncSetAttribute(gemm_bfhl<2>, cudaFuncAttributeMaxDynamicSharedMemorySize, GSM);
    cudaFuncSetAttribute(gemm_bfhl<3>, cudaFuncAttributeMaxDynamicSharedMemorySize, GSM);
    cudaFuncSetAttribute(attn_f16,     cudaFuncAttributeMaxDynamicSharedMemorySize, ASMB);

    split_x<<<Mtot * Dd / 4 / 256, 256>>>(x, xh, xl);
    split_wt4<<<dim3(32, 32, 4), 256>>>(Wq, Wk, Wv, Wo, wth, wtl);

    dim3 gGrid(Dd / 128, Mtot / 128);
    gemm_bfhl<2><<<gGrid, 128, GSM>>>(xh, xl, wth + 0u * Dd * Dd, wtl + 0u * Dd * Dd,
                                      bq, 0.125f, nullptr, qh, ql);
    gemm_bfhl<3><<<gGrid, 128, GSM>>>(xh, xl, wth + 1u * Dd * Dd, wtl + 1u * Dd * Dd,
                                      bk, 1.0f, nullptr, kh, nullptr);
    gemm_bfhl<2><<<gGrid, 128, GSM>>>(xh, xl, wth + 2u * Dd * Dd, wtl + 2u * Dd * Dd,
                                      bv, 1.0f, nullptr, vh, vl);

    attn_f16<<<dim3(Bb * Hh, Ss / 256), 256, ASMB>>>(qh, ql, kh, vh, vl, oh, ol);

    gemm_bfhl<0><<<gGrid, 128, GSM>>>(oh, ol, wth + 3u * Dd * Dd, wtl + 3u * Dd * Dd,
                                      bo, 1.0f, out, nullptr, nullptr);
}

// round 10
// speedup vs baseline: 6.3380x; 1.0074x over previous
#include <cuda_runtime.h>
#include <cuda_bf16.h>
#include <cuda_fp16.h>
#include <cstdint>

#define Bb   2
#define Ss   2048
#define Dd   1024
#define Hh   16
#define DKh  64
#define Mtot (Bb * Ss)

typedef __nv_bfloat16 bf16;

__device__ bf16 g_xh[Mtot * Dd], g_xl[Mtot * Dd];
__device__ bf16 g_wth[4u * Dd * Dd], g_wtl[4u * Dd * Dd];
__device__ __half g_qh[Mtot * Dd], g_ql[Mtot * Dd];
__device__ __half g_kh[Mtot * Dd];
__device__ __half g_vh[Mtot * Dd], g_vl[Mtot * Dd];
__device__ bf16 g_oh[Mtot * Dd], g_ol[Mtot * Dd];

// ---------------- PTX helpers ----------------
__device__ __forceinline__ uint32_t smem_u32(const void* p) {
    uint32_t a;
    asm("{ .reg .u64 t; cvta.to.shared.u64 t, %1; cvt.u32.u64 %0, t; }" : "=r"(a) : "l"(p));
    return a;
}
__device__ __forceinline__ void cpa16(uint32_t dst, const void* src) {
    asm volatile("cp.async.ca.shared.global [%0], [%1], 16;" :: "r"(dst), "l"(src));
}
#define CP_COMMIT() asm volatile("cp.async.commit_group;" ::: "memory")
#define CP_WAIT(n)  asm volatile("cp.async.wait_group %0;" :: "n"(n) : "memory")

__device__ __forceinline__ void mma_bf16(float* c, const uint32_t* a, uint32_t b0, uint32_t b1)
{
    asm volatile(
        "mma.sync.aligned.m16n8k16.row.col.f32.bf16.bf16.f32 "
        "{%0,%1,%2,%3},{%4,%5,%6,%7},{%8,%9},{%0,%1,%2,%3};"
        : "+f"(c[0]), "+f"(c[1]), "+f"(c[2]), "+f"(c[3])
        : "r"(a[0]), "r"(a[1]), "r"(a[2]), "r"(a[3]), "r"(b0), "r"(b1));
}
__device__ __forceinline__ void mma_f16(float* c, const uint32_t* a, uint32_t b0, uint32_t b1)
{
    asm volatile(
        "mma.sync.aligned.m16n8k16.row.col.f32.f16.f16.f32 "
        "{%0,%1,%2,%3},{%4,%5,%6,%7},{%8,%9},{%0,%1,%2,%3};"
        : "+f"(c[0]), "+f"(c[1]), "+f"(c[2]), "+f"(c[3])
        : "r"(a[0]), "r"(a[1]), "r"(a[2]), "r"(a[3]), "r"(b0), "r"(b1));
}
__device__ __forceinline__ void ldmx4(uint32_t* r, uint32_t addr)
{
    asm volatile("ldmatrix.sync.aligned.m8n8.x4.shared.b16 {%0,%1,%2,%3}, [%4];"
        : "=r"(r[0]), "=r"(r[1]), "=r"(r[2]), "=r"(r[3]) : "r"(addr));
}
__device__ __forceinline__ void ldmx4t(uint32_t* r, uint32_t addr)
{
    asm volatile("ldmatrix.sync.aligned.m8n8.x4.trans.shared.b16 {%0,%1,%2,%3}, [%4];"
        : "=r"(r[0]), "=r"(r[1]), "=r"(r[2]), "=r"(r[3]) : "r"(addr));
}
__device__ __forceinline__ void packhl(float a, float b, uint32_t& hi, uint32_t& lo)
{
    __nv_bfloat162 h = __float22bfloat162_rn(make_float2(a, b));
    float2 hf = __bfloat1622float2(h);
    __nv_bfloat162 l = __float22bfloat162_rn(make_float2(a - hf.x, b - hf.y));
    hi = *(uint32_t*)&h; lo = *(uint32_t*)&l;
}
__device__ __forceinline__ uint32_t packf16(float a, float b)
{
    __half2 h = __floats2half2_rn(a, b);
    return *(uint32_t*)&h;
}

// ---------------------------------------------------------------------------
// Prep kernels
// ---------------------------------------------------------------------------
__global__ __launch_bounds__(256) void split_x(const float* __restrict__ X,
                                               bf16* __restrict__ Xh, bf16* __restrict__ Xl)
{
    int i = blockIdx.x * 256 + threadIdx.x;
    float4 v = ((const float4*)X)[i];
    uint32_t h0, l0, h1, l1;
    packhl(v.x, v.y, h0, l0);
    packhl(v.z, v.w, h1, l1);
    ((uint2*)Xh)[i] = make_uint2(h0, h1);
    ((uint2*)Xl)[i] = make_uint2(l0, l1);
}

__global__ __launch_bounds__(256) void split_wt4(
    const float* __restrict__ W0, const float* __restrict__ W1,
    const float* __restrict__ W2, const float* __restrict__ W3,
    bf16* __restrict__ Wth, bf16* __restrict__ Wtl)
{
    __shared__ float tile[32][33];
    const float* W = (blockIdx.z == 0) ? W0 : (blockIdx.z == 1) ? W1 : (blockIdx.z == 2) ? W2 : W3;
    bf16* oh = Wth + (size_t)blockIdx.z * Dd * Dd;
    bf16* ol = Wtl + (size_t)blockIdx.z * Dd * Dd;
    int bx = blockIdx.x * 32, by = blockIdx.y * 32;
    int tx = threadIdx.x & 31, ty8 = threadIdx.x >> 5;
#pragma unroll
    for (int i = 0; i < 4; i++)
        tile[ty8 + i * 8][tx] = W[(size_t)(by + ty8 + i * 8) * Dd + bx + tx];
    __syncthreads();
#pragma unroll
    for (int i = 0; i < 4; i++) {
        float v = tile[tx][ty8 + i * 8];
        bf16 h = __float2bfloat16_rn(v);
        bf16 lo = __float2bfloat16_rn(v - __bfloat162float(h));
        size_t idx = (size_t)(bx + ty8 + i * 8) * Dd + by + tx;
        oh[idx] = h; ol[idx] = lo;
    }
}

// ---------------------------------------------------------------------------
// 3xBF16 GEMM. OUT: 0 fp32, 1 bf16 hi/lo, 2 fp16 hi/lo, 3 fp16 single.
// MMAs issued term-major so consecutive MMAs hit different accumulators.
// ---------------------------------------------------------------------------
#define GRS  40
#define GT_AL (128 * GRS)
#define GT_B  (2 * 128 * GRS)
#define GT_BL (3 * 128 * GRS)
#define GBUF  (4 * 128 * GRS)
#define GSM   (2 * GBUF * 2)

extern __shared__ __align__(16) char dynsm[];

template<int OUT>
__global__ __launch_bounds__(128, 2) void gemm_bfhl(
    const bf16* __restrict__ Ah, const bf16* __restrict__ Al,
    const bf16* __restrict__ Bh, const bf16* __restrict__ Bl,
    const float* __restrict__ bias, float scale,
    float* __restrict__ C, void* __restrict__ ChV, void* __restrict__ ClV)
{
    bf16* sm = (bf16*)dynsm;
    const int t = threadIdx.x, l = t & 31, wid = t >> 5;
    const int wm = wid >> 1, wn = wid & 1;
    const int row0 = blockIdx.y * 128, col0 = blockIdx.x * 128;
    const int lr = l >> 2, lc2 = (l & 3) * 2;
    const uint32_t sb = smem_u32(sm);

    float acc[4][8][4];
#pragma unroll
    for (int mt = 0; mt < 4; mt++)
#pragma unroll
        for (int nt = 0; nt < 8; nt++)
#pragma unroll
            for (int j = 0; j < 4; j++) acc[mt][nt][j] = 0.f;

    const int gr = t >> 2, gc8 = (t & 3) * 8;

    auto load = [&](int ch, int buf) {
        const int k0 = ch * 32;
        const uint32_t base = sb + buf * GBUF * 2;
#pragma unroll
        for (int i = 0; i < 4; i++) {
            int r = gr + i * 32;
            uint32_t doff = (r * GRS + gc8) * 2;
            cpa16(base + doff,             Ah + (size_t)(row0 + r) * Dd + k0 + gc8);
            cpa16(base + GT_AL * 2 + doff, Al + (size_t)(row0 + r) * Dd + k0 + gc8);
            cpa16(base + GT_B * 2 + doff,  Bh + (size_t)(col0 + r) * Dd + k0 + gc8);
            cpa16(base + GT_BL * 2 + doff, Bl + (size_t)(col0 + r) * Dd + k0 + gc8);
        }
    };

    const int arow = l & 15, ako = (l >> 4) * 8;
    const int brow = (l & 7) + ((l >> 1) & 8), bko = l & 8;

    load(0, 0); CP_COMMIT();

    for (int ch = 0; ch < 32; ch++) {
        if (ch < 31) { load(ch + 1, (ch + 1) & 1); CP_COMMIT(); CP_WAIT(1); }
        else CP_WAIT(0);
        __syncthreads();

        const uint32_t bufb = sb + (ch & 1) * GBUF * 2;
        const uint32_t aHb = bufb + ((wm * 64 + arow) * GRS + ako) * 2;
        const uint32_t aLb = aHb + GT_AL * 2;
        const uint32_t bHb = bufb + GT_B * 2 + ((wn * 64 + brow) * GRS + bko) * 2;
        const uint32_t bLb = bHb + (GT_BL - GT_B) * 2;

#pragma unroll
        for (int kk = 0; kk < 2; kk++) {
            const uint32_t kb2 = kk * 32;
            uint32_t ah[4][4], al[4][4];
#pragma unroll
            for (int mt = 0; mt < 4; mt++) {
                ldmx4(ah[mt], aHb + mt * (16 * GRS * 2) + kb2);
                ldmx4(al[mt], aLb + mt * (16 * GRS * 2) + kb2);
            }
#pragma unroll
            for (int nt2 = 0; nt2 < 4; nt2++) {
                uint32_t bh[4], bl[4];
                ldmx4(bh, bHb + nt2 * (16 * GRS * 2) + kb2);
                ldmx4(bl, bLb + nt2 * (16 * GRS * 2) + kb2);
                // term-major: consecutive MMAs hit different accumulators
#pragma unroll
                for (int mt = 0; mt < 4; mt++)
                    mma_bf16(acc[mt][2 * nt2],     ah[mt], bh[0], bh[1]);
#pragma unroll
                for (int mt = 0; mt < 4; mt++)
                    mma_bf16(acc[mt][2 * nt2 + 1], ah[mt], bh[2], bh[3]);
#pragma unroll
                for (int mt = 0; mt < 4; mt++)
                    mma_bf16(acc[mt][2 * nt2],     ah[mt], bl[0], bl[1]);
#pragma unroll
                for (int mt = 0; mt < 4; mt++)
                    mma_bf16(acc[mt][2 * nt2 + 1], ah[mt], bl[2], bl[3]);
#pragma unroll
                for (int mt = 0; mt < 4; mt++)
                    mma_bf16(acc[mt][2 * nt2],     al[mt], bh[0], bh[1]);
#pragma unroll
                for (int mt = 0; mt < 4; mt++)
                    mma_bf16(acc[mt][2 * nt2 + 1], al[mt], bh[2], bh[3]);
            }
        }
        __syncthreads();
    }

#pragma unroll
    for (int mt = 0; mt < 4; mt++) {
        const int r = row0 + wm * 64 + mt * 16 + lr;
#pragma unroll
        for (int nt = 0; nt < 8; nt++) {
            const int c = col0 + wn * 64 + nt * 8 + lc2;
            float2 bb = *(const float2*)&bias[c];
            float p0 = (acc[mt][nt][0] + bb.x) * scale;
            float p1 = (acc[mt][nt][1] + bb.y) * scale;
            float p2 = (acc[mt][nt][2] + bb.x) * scale;
            float p3 = (acc[mt][nt][3] + bb.y) * scale;
            if (OUT == 0) {
                *(float2*)(C + (size_t)r * Dd + c)       = make_float2(p0, p1);
                *(float2*)(C + (size_t)(r + 8) * Dd + c) = make_float2(p2, p3);
            } else if (OUT == 1) {
                bf16* Ch = (bf16*)ChV; bf16* Cl = (bf16*)ClV;
                uint32_t hi, lo;
                packhl(p0, p1, hi, lo);
                *(uint32_t*)&Ch[(size_t)r * Dd + c] = hi;
                *(uint32_t*)&Cl[(size_t)r * Dd + c] = lo;
                packhl(p2, p3, hi, lo);
                *(uint32_t*)&Ch[(size_t)(r + 8) * Dd + c] = hi;
                *(uint32_t*)&Cl[(size_t)(r + 8) * Dd + c] = lo;
            } else if (OUT == 2) {
                __half* Ch = (__half*)ChV; __half* Cl = (__half*)ClV;
                __half2 h = __floats2half2_rn(p0, p1);
                float2 hf = __half22float2(h);
                __half2 lo = __floats2half2_rn(p0 - hf.x, p1 - hf.y);
                *(__half2*)&Ch[(size_t)r * Dd + c] = h;
                *(__half2*)&Cl[(size_t)r * Dd + c] = lo;
                h = __floats2half2_rn(p2, p3);
                hf = __half22float2(h);
                lo = __floats2half2_rn(p2 - hf.x, p3 - hf.y);
                *(__half2*)&Ch[(size_t)(r + 8) * Dd + c] = h;
                *(__half2*)&Cl[(size_t)(r + 8) * Dd + c] = lo;
            } else {
                __half* Ch = (__half*)ChV;
                *(__half2*)&Ch[(size_t)r * Dd + c]       = __floats2half2_rn(p0, p1);
                *(__half2*)&Ch[(size_t)(r + 8) * Dd + c] = __floats2half2_rn(p2, p3);
            }
        }
    }
}

// ---------------------------------------------------------------------------
// Flash attention. QK: fp16 2-term (Q hi/lo regs, K single). PV: fp16 2-term.
// CTA = (b,h) x 256 queries; 8 warps x 32 rows. 64 keys/chunk, 3-stage pipe.
// MMAs issued term-major (dependency distance >= 4).
// ---------------------------------------------------------------------------
#define ARS 72
#define AQL (256 * ARS)
#define AKV0 (2 * 256 * ARS)
#define KVB (3 * 64 * ARS)
#define ASMB ((AKV0 + 3 * KVB) * 2)   // 156672 bytes

__global__ __launch_bounds__(256, 1) void attn_f16(
    const __half* __restrict__ Qh, const __half* __restrict__ Ql,
    const __half* __restrict__ Kh,
    const __half* __restrict__ Vh, const __half* __restrict__ Vl,
    bf16* __restrict__ Oh, bf16* __restrict__ Ol)
{
    __half* sm = (__half*)dynsm;
    const int t = threadIdx.x, l = t & 31, wid = t >> 5;
    const int lr = l >> 2, lc2 = (l & 3) * 2;
    const int b = blockIdx.x >> 4, h = blockIdx.x & 15, hc = h * DKh;
    const int q0 = blockIdx.y * 256, wrow = wid * 32;
    const uint32_t sb = smem_u32(sm);
    const int vkey = l & 15, vdks = (l >> 4) * 8;
    const int krow = (l & 7) + ((l >> 1) & 8), kko = l & 8;

    const size_t qoff = (size_t)(b * Ss + q0) * Dd + hc;
    const size_t kvrow0 = (size_t)(b * Ss) * Dd + hc;

    {
        const int r = t >> 3, c8 = (t & 7) * 8;
#pragma unroll
        for (int i = 0; i < 8; i++) {
            int rr = r + i * 32;
            uint32_t doff = (rr * ARS + c8) * 2;
            cpa16(sb + doff,           Qh + qoff + (size_t)rr * Dd + c8);
            cpa16(sb + AQL * 2 + doff, Ql + qoff + (size_t)rr * Dd + c8);
        }
    }
    CP_COMMIT();

    auto loadKV = [&](int ck, int buf) {
        const size_t koff = kvrow0 + (size_t)ck * 64 * Dd;
        const uint32_t base = sb + (AKV0 + buf * KVB) * 2;
        const int r = t >> 3, c8 = (t & 7) * 8;
#pragma unroll
        for (int i = 0; i < 2; i++) {
            int rr = r + i * 32;
            uint32_t doff = (rr * ARS + c8) * 2;
            const size_t goff = koff + (size_t)rr * Dd + c8;
            cpa16(base + doff,                    Kh + goff);
            cpa16(base + 1 * 64 * ARS * 2 + doff, Vh + goff);
            cpa16(base + 2 * 64 * ARS * 2 + doff, Vl + goff);
        }
    };
    loadKV(0, 0); CP_COMMIT();
    loadKV(1, 1); CP_COMMIT();

    CP_WAIT(2);
    __syncthreads();

    uint32_t qhf[2][4][4], qlf[2][4][4];
#pragma unroll
    for (int mt = 0; mt < 2; mt++)
#pragma unroll
        for (int kc = 0; kc < 4; kc++)
#pragma unroll
            for (int j = 0; j < 4; j++) {
                int rr = wrow + mt * 16 + lr + (j & 1) * 8;
                int cc = kc * 16 + (j >> 1) * 8 + lc2;
                qhf[mt][kc][j] = *(const uint32_t*)&sm[rr * ARS + cc];
                qlf[mt][kc][j] = *(const uint32_t*)&sm[AQL + rr * ARS + cc];
            }

    float mrow[2][2], lrow[2][2];
    float o[2][8][4];
#pragma unroll
    for (int mt = 0; mt < 2; mt++) {
        mrow[mt][0] = mrow[mt][1] = -INFINITY;
        lrow[mt][0] = lrow[mt][1] = 0.f;
#pragma unroll
        for (int nt = 0; nt < 8; nt++)
#pragma unroll
            for (int j = 0; j < 4; j++) o[mt][nt][j] = 0.f;
    }

    for (int ck = 0; ck < 32; ck++) {
        CP_WAIT(1);
        __syncthreads();
        if (ck + 2 < 32) { loadKV(ck + 2, (ck + 2) % 3); CP_COMMIT(); }

        const int buf = ck % 3;
        const uint32_t kvb = sb + (AKV0 + buf * KVB) * 2;
        const uint32_t kHb = kvb + (krow * ARS + kko) * 2;
        const uint32_t vh32 = kvb + 64 * ARS * 2;
        const uint32_t vl32 = vh32 + 64 * ARS * 2;

        // S = Q K^T : term-major issue
        float s[2][8][4];
#pragma unroll
        for (int mt = 0; mt < 2; mt++)
#pragma unroll
            for (int nt = 0; nt < 8; nt++)
                s[mt][nt][0] = s[mt][nt][1] = s[mt][nt][2] = s[mt][nt][3] = 0.f;
#pragma unroll
        for (int nt2 = 0; nt2 < 4; nt2++) {
#pragma unroll
            for (int kc = 0; kc < 4; kc++) {
                uint32_t kh4[4];
                ldmx4(kh4, kHb + nt2 * (16 * ARS * 2) + kc * 32);
                mma_f16(s[0][2 * nt2],     qhf[0][kc], kh4[0], kh4[1]);
                mma_f16(s[1][2 * nt2],     qhf[1][kc], kh4[0], kh4[1]);
                mma_f16(s[0][2 * nt2 + 1], qhf[0][kc], kh4[2], kh4[3]);
                mma_f16(s[1][2 * nt2 + 1], qhf[1][kc], kh4[2], kh4[3]);
                mma_f16(s[0][2 * nt2],     qlf[0][kc], kh4[0], kh4[1]);
                mma_f16(s[1][2 * nt2],     qlf[1][kc], kh4[0], kh4[1]);
                mma_f16(s[0][2 * nt2 + 1], qlf[0][kc], kh4[2], kh4[3]);
                mma_f16(s[1][2 * nt2 + 1], qlf[1][kc], kh4[2], kh4[3]);
            }
        }

        // online softmax
#pragma unroll
        for (int mt = 0; mt < 2; mt++) {
            float mx0 = s[mt][0][0], mx1 = s[mt][0][2];
#pragma unroll
            for (int nt = 0; nt < 8; nt++) {
                mx0 = fmaxf(mx0, fmaxf(s[mt][nt][0], s[mt][nt][1]));
                mx1 = fmaxf(mx1, fmaxf(s[mt][nt][2], s[mt][nt][3]));
            }
            mx0 = fmaxf(mx0, __shfl_xor_sync(0xffffffffu, mx0, 1));
            mx0 = fmaxf(mx0, __shfl_xor_sync(0xffffffffu, mx0, 2));
            mx1 = fmaxf(mx1, __shfl_xor_sync(0xffffffffu, mx1, 1));
            mx1 = fmaxf(mx1, __shfl_xor_sync(0xffffffffu, mx1, 2));
            float mn0 = fmaxf(mrow[mt][0], mx0), mn1 = fmaxf(mrow[mt][1], mx1);
            float c0 = __expf(mrow[mt][0] - mn0), c1 = __expf(mrow[mt][1] - mn1);
            mrow[mt][0] = mn0; mrow[mt][1] = mn1;
            float sum0 = 0.f, sum1 = 0.f;
#pragma unroll
            for (int nt = 0; nt < 8; nt++) {
                s[mt][nt][0] = __expf(s[mt][nt][0] - mn0);
                s[mt][nt][1] = __expf(s[mt][nt][1] - mn0);
                s[mt][nt][2] = __expf(s[mt][nt][2] - mn1);
                s[mt][nt][3] = __expf(s[mt][nt][3] - mn1);
                sum0 += s[mt][nt][0] + s[mt][nt][1];
                sum1 += s[mt][nt][2] + s[mt][nt][3];
            }
            sum0 += __shfl_xor_sync(0xffffffffu, sum0, 1);
            sum0 += __shfl_xor_sync(0xffffffffu, sum0, 2);
            sum1 += __shfl_xor_sync(0xffffffffu, sum1, 1);
            sum1 += __shfl_xor_sync(0xffffffffu, sum1, 2);
            lrow[mt][0] = lrow[mt][0] * c0 + sum0;
            lrow[mt][1] = lrow[mt][1] * c1 + sum1;
#pragma unroll
            for (int nt = 0; nt < 8; nt++) {
                o[mt][nt][0] *= c0; o[mt][nt][1] *= c0;
                o[mt][nt][2] *= c1; o[mt][nt][3] *= c1;
            }
        }

        // O += P @ V : term-major issue
#pragma unroll
        for (int kc = 0; kc < 4; kc++) {
            uint32_t pf[2][4];
#pragma unroll
            for (int mt = 0; mt < 2; mt++) {
                pf[mt][0] = packf16(s[mt][2 * kc][0],     s[mt][2 * kc][1]);
                pf[mt][1] = packf16(s[mt][2 * kc][2],     s[mt][2 * kc][3]);
                pf[mt][2] = packf16(s[mt][2 * kc + 1][0], s[mt][2 * kc + 1][1]);
                pf[mt][3] = packf16(s[mt][2 * kc + 1][2], s[mt][2 * kc + 1][3]);
            }
            const uint32_t rowoff = ((kc * 16 + vkey) * ARS + vdks) * 2;
#pragma unroll
            for (int np = 0; np < 4; np++) {
                uint32_t rh[4], rl[4];
                ldmx4t(rh, vh32 + rowoff + np * 32);
                ldmx4t(rl, vl32 + rowoff + np * 32);
                mma_f16(o[0][2 * np],     pf[0], rh[0], rh[1]);
                mma_f16(o[1][2 * np],     pf[1], rh[0], rh[1]);
                mma_f16(o[0][2 * np + 1], pf[0], rh[2], rh[3]);
                mma_f16(o[1][2 * np + 1], pf[1], rh[2], rh[3]);
                mma_f16(o[0][2 * np],     pf[0], rl[0], rl[1]);
                mma_f16(o[1][2 * np],     pf[1], rl[0], rl[1]);
                mma_f16(o[0][2 * np + 1], pf[0], rl[2], rl[3]);
                mma_f16(o[1][2 * np + 1], pf[1], rl[2], rl[3]);
            }
        }
    }

    // finalize
#pragma unroll
    for (int mt = 0; mt < 2; mt++) {
        float i0 = 1.f / lrow[mt][0], i1 = 1.f / lrow[mt][1];
        const size_t r0 = (size_t)(b * Ss + q0 + wrow + mt * 16 + lr) * Dd + hc;
#pragma unroll
        for (int nt = 0; nt < 8; nt++) {
            uint32_t hi, lo;
            packhl(o[mt][nt][0] * i0, o[mt][nt][1] * i0, hi, lo);
            *(uint32_t*)&Oh[r0 + nt * 8 + lc2] = hi;
            *(uint32_t*)&Ol[r0 + nt * 8 + lc2] = lo;
            packhl(o[mt][nt][2] * i1, o[mt][nt][3] * i1, hi, lo);
            *(uint32_t*)&Oh[r0 + 8 * Dd + nt * 8 + lc2] = hi;
            *(uint32_t*)&Ol[r0 + 8 * Dd + nt * 8 + lc2] = lo;
        }
    }
}

// ---------------------------------------------------------------------------
extern "C" void kernel_launch(void* const* d_in, const int* in_sizes, int n_in,
                              void* d_out, int out_size)
{
    const float* x  = (const float*)d_in[0];
    const float* Wq = (const float*)d_in[1];
    const float* bq = (const float*)d_in[2];
    const float* Wk = (const float*)d_in[3];
    const float* bk = (const float*)d_in[4];
    const float* Wv = (const float*)d_in[5];
    const float* bv = (const float*)d_in[6];
    const float* Wo = (const float*)d_in[7];
    const float* bo = (const float*)d_in[8];
    float* out = (float*)d_out;

    bf16 *xh, *xl, *wth, *wtl, *oh, *ol;
    __half *qh, *ql, *kh, *vh, *vl;
    cudaGetSymbolAddress((void**)&xh, g_xh);  cudaGetSymbolAddress((void**)&xl, g_xl);
    cudaGetSymbolAddress((void**)&wth, g_wth); cudaGetSymbolAddress((void**)&wtl, g_wtl);
    cudaGetSymbolAddress((void**)&qh, g_qh);  cudaGetSymbolAddress((void**)&ql, g_ql);
    cudaGetSymbolAddress((void**)&kh, g_kh);
    cudaGetSymbolAddress((void**)&vh, g_vh);  cudaGetSymbolAddress((void**)&vl, g_vl);
    cudaGetSymbolAddress((void**)&oh, g_oh);  cudaGetSymbolAddress((void**)&ol, g_ol);

    cudaFuncSetAttribute(gemm_bfhl<0>, cudaFuncAttributeMaxDynamicSharedMemorySize, GSM);
    cudaFuncSetAttribute(gemm_bfhl<2>, cudaFuncAttributeMaxDynamicSharedMemorySize, GSM);
    cudaFuncSetAttribute(gemm_bfhl<3>, cudaFuncAttributeMaxDynamicSharedMemorySize, GSM);
    cudaFuncSetAttribute(attn_f16,     cudaFuncAttributeMaxDynamicSharedMemorySize, ASMB);

    split_x<<<Mtot * Dd / 4 / 256, 256>>>(x, xh, xl);
    split_wt4<<<dim3(32, 32, 4), 256>>>(Wq, Wk, Wv, Wo, wth, wtl);

    dim3 gGrid(Dd / 128, Mtot / 128);
    gemm_bfhl<2><<<gGrid, 128, GSM>>>(xh, xl, wth + 0u * Dd * Dd, wtl + 0u * Dd * Dd,
                                      bq, 0.125f, nullptr, qh, ql);
    gemm_bfhl<3><<<gGrid, 128, GSM>>>(xh, xl, wth + 1u * Dd * Dd, wtl + 1u * Dd * Dd,
                                      bk, 1.0f, nullptr, kh, nullptr);
    gemm_bfhl<2><<<gGrid, 128, GSM>>>(xh, xl, wth + 2u * Dd * Dd, wtl + 2u * Dd * Dd,
                                      bv, 1.0f, nullptr, vh, vl);

    attn_f16<<<dim3(Bb * Hh, Ss / 256), 256, ASMB>>>(qh, ql, kh, vh, vl, oh, ol);

    gemm_bfhl<0><<<gGrid, 128, GSM>>>(oh, ol, wth + 3u * Dd * Dd, wtl + 3u * Dd * Dd,
                                      bo, 1.0f, out, nullptr, nullptr);
}